// round 5
// baseline (speedup 1.0000x reference)
#include <cuda_runtime.h>
#include <math.h>
#include <cstdint>

#define Bc   4
#define Sc   2048
#define Dc   2048
#define LATc 512
#define NHc  16
#define NKVc 4
#define HDc  32
#define KVDc 128
#define Tc   (Bc * Sc)
#define GAINc 0.25f
#define EPSc  1e-6f

// weight offsets inside the packed split-weight arrays
#define OFF_WQ 0
#define OFF_WK (LATc * Dc)                    // 1048576
#define OFF_WV (OFF_WK + KVDc * Dc)           // 1310720
#define OFF_WO (OFF_WV + KVDc * Dc)           // 1572864
#define WTOT   (OFF_WO + Dc * LATc)           // 2621440

// -------- scratch (device globals; no allocation allowed) --------
__device__ float g_q [Tc * LATc];
__device__ float g_k [Tc * KVDc];
__device__ float g_v [Tc * KVDc];
__device__ float g_qc[Tc * LATc];
__device__ float g_kc[Tc * KVDc];
__device__ float g_qm[Tc * HDc];
__device__ float g_km[Tc * HDc];
__device__ float g_o [Tc * LATc];
__device__ float g_xh[Tc * Dc];
__device__ float g_xl[Tc * Dc];
__device__ float g_wh[WTOT];
__device__ float g_wl[WTOT];
__device__ float g_ph[Tc * LATc];
__device__ float g_pl[Tc * LATc];

// ---------------- helpers ----------------
__device__ __forceinline__ void mma_tf32(float* d, uint32_t a0, uint32_t a1,
                                         uint32_t a2, uint32_t a3,
                                         uint32_t b0, uint32_t b1) {
    asm volatile(
        "mma.sync.aligned.m16n8k8.row.col.f32.tf32.tf32.f32 "
        "{%0,%1,%2,%3}, {%4,%5,%6,%7}, {%8,%9}, {%0,%1,%2,%3};"
        : "+f"(d[0]), "+f"(d[1]), "+f"(d[2]), "+f"(d[3])
        : "r"(a0), "r"(a1), "r"(a2), "r"(a3), "r"(b0), "r"(b1));
}
__device__ __forceinline__ void split_tf32(float x, float& hi, float& lo) {
    uint32_t h;
    asm("cvt.rna.tf32.f32 %0, %1;" : "=r"(h) : "f"(x));
    float r = x - __uint_as_float(h);
    uint32_t l;
    asm("cvt.rna.tf32.f32 %0, %1;" : "=r"(l) : "f"(r));
    hi = __uint_as_float(h); lo = __uint_as_float(l);
}
__device__ __forceinline__ uint32_t smem_u32(const void* p) {
    uint32_t a;
    asm("{ .reg .u64 t; cvta.to.shared.u64 t, %1; cvt.u32.u64 %0, t; }" : "=r"(a) : "l"(p));
    return a;
}
#define CP_ASYNC16(dst, src) \
    asm volatile("cp.async.cg.shared.global [%0], [%1], 16;" :: "r"(dst), "l"(src))
#define CP_COMMIT() asm volatile("cp.async.commit_group;" ::: "memory")
#define CP_WAIT(n)  asm volatile("cp.async.wait_group %0;" :: "n"(n) : "memory")

// ============================================================
// split array into tf32 hi/lo (vectorized)
// ============================================================
__global__ void __launch_bounds__(256) split_arr(
    float* __restrict__ hi, float* __restrict__ lo,
    const float* __restrict__ src, int n4)
{
    int i = blockIdx.x * 256 + threadIdx.x;
    if (i >= n4) return;
    float4 v = ((const float4*)src)[i];
    float4 h, l;
    split_tf32(v.x, h.x, l.x);
    split_tf32(v.y, h.y, l.y);
    split_tf32(v.z, h.z, l.z);
    split_tf32(v.w, h.w, l.w);
    ((float4*)hi)[i] = h;
    ((float4*)lo)[i] = l;
}

// ============================================================
// tf32-split GEMM, fully pre-split operands: no cvt in loop.
// C[M,N] = A[M,K]*B[N,K]^T; 128x128 tile, K-chunk 32, 3 stages.
// ============================================================
#define TSTRIDE 36
#define ABYTES  (128 * TSTRIDE * 4)      // 18432
#define SBYTES  (4 * ABYTES)             // Ah, Al, Bh, Bl per stage
#define GEMM_SMEM (3 * SBYTES)           // 221184 B

__global__ void __launch_bounds__(256, 1) gemm_pre(
    const float* __restrict__ Ah, const float* __restrict__ Al, int K,
    const float* __restrict__ Wh, const float* __restrict__ Wl,
    size_t off0, float* __restrict__ C0, int nx0, int N0,
    size_t off1, float* __restrict__ C1,
    size_t off2, float* __restrict__ C2)
{
    extern __shared__ char sm[];
    const int tid = threadIdx.x;
    const int wid = tid >> 5;
    const int lane = tid & 31;
    const int lr = lane >> 2;
    const int lc = lane & 3;
    const int wm = wid & 3;
    const int wn = wid >> 2;

    int bx = blockIdx.x;
    size_t woff;
    float* Cp;
    int N;
    if (bx < nx0)       { woff = off0; Cp = C0; N = N0; }
    else if (bx == nx0) { woff = off1; Cp = C1; N = 128; bx = 0; }
    else                { woff = off2; Cp = C2; N = 128; bx = 0; }
    const float* Bh = Wh + woff;
    const float* Bl = Wl + woff;
    const int m0 = blockIdx.y * 128;
    const int n0 = bx * 128;
    const int NC = K >> 5;

    const uint32_t smb = smem_u32(sm);
    int grow[4], gc16[4];
    uint32_t sdst[4];
#pragma unroll
    for (int j = 0; j < 4; j++) {
        int seg = tid + j * 256;
        grow[j] = seg >> 3;
        gc16[j] = seg & 7;
        sdst[j] = (uint32_t)(grow[j] * (TSTRIDE * 4) + gc16[j] * 16);
    }

    float acc[2][8][4];
#pragma unroll
    for (int mt = 0; mt < 2; mt++)
#pragma unroll
        for (int nt = 0; nt < 8; nt++)
#pragma unroll
            for (int c = 0; c < 4; c++) acc[mt][nt][c] = 0.f;

    // prefetch chunks 0, 1
#pragma unroll
    for (int pc = 0; pc < 2; pc++) {
        const uint32_t so = smb + (uint32_t)pc * SBYTES;
        const int kt = pc << 5;
#pragma unroll
        for (int j = 0; j < 4; j++) {
            size_t ao = (size_t)(m0 + grow[j]) * K + kt + gc16[j] * 4;
            size_t bo = (size_t)(n0 + grow[j]) * K + kt + gc16[j] * 4;
            CP_ASYNC16(so + sdst[j],              Ah + ao);
            CP_ASYNC16(so + ABYTES + sdst[j],     Al + ao);
            CP_ASYNC16(so + 2 * ABYTES + sdst[j], Bh + bo);
            CP_ASYNC16(so + 3 * ABYTES + sdst[j], Bl + bo);
        }
        CP_COMMIT();
    }

    int bufi = 0;
    for (int i = 0; i < NC; i++) {
        if (i + 2 < NC) {
            int dsti = bufi + 2; if (dsti >= 3) dsti -= 3;
            const uint32_t so = smb + (uint32_t)dsti * SBYTES;
            const int kt = (i + 2) << 5;
#pragma unroll
            for (int j = 0; j < 4; j++) {
                size_t ao = (size_t)(m0 + grow[j]) * K + kt + gc16[j] * 4;
                size_t bo = (size_t)(n0 + grow[j]) * K + kt + gc16[j] * 4;
                CP_ASYNC16(so + sdst[j],              Ah + ao);
                CP_ASYNC16(so + ABYTES + sdst[j],     Al + ao);
                CP_ASYNC16(so + 2 * ABYTES + sdst[j], Bh + bo);
                CP_ASYNC16(so + 3 * ABYTES + sdst[j], Bl + bo);
            }
        }
        CP_COMMIT();
        CP_WAIT(2);
        __syncthreads();

        const uint32_t* Ahs = (const uint32_t*)(sm + (size_t)bufi * SBYTES);
        const uint32_t* Als = (const uint32_t*)(sm + (size_t)bufi * SBYTES + ABYTES);
        const uint32_t* Bhs = (const uint32_t*)(sm + (size_t)bufi * SBYTES + 2 * ABYTES);
        const uint32_t* Bls = (const uint32_t*)(sm + (size_t)bufi * SBYTES + 3 * ABYTES);

#pragma unroll
        for (int ks = 0; ks < 4; ks++) {
            const int kc = ks * 8 + lc;
            uint32_t ah[2][4], al[2][4];
#pragma unroll
            for (int mt = 0; mt < 2; mt++) {
                const int r = wm * 32 + mt * 16 + lr;
                ah[mt][0] = Ahs[r * TSTRIDE + kc];
                ah[mt][1] = Ahs[(r + 8) * TSTRIDE + kc];
                ah[mt][2] = Ahs[r * TSTRIDE + kc + 4];
                ah[mt][3] = Ahs[(r + 8) * TSTRIDE + kc + 4];
                al[mt][0] = Als[r * TSTRIDE + kc];
                al[mt][1] = Als[(r + 8) * TSTRIDE + kc];
                al[mt][2] = Als[r * TSTRIDE + kc + 4];
                al[mt][3] = Als[(r + 8) * TSTRIDE + kc + 4];
            }
            uint32_t bh[8][2], bl[8][2];
#pragma unroll
            for (int nt = 0; nt < 8; nt++) {
                const int n = wn * 64 + nt * 8 + lr;
                bh[nt][0] = Bhs[n * TSTRIDE + kc];
                bh[nt][1] = Bhs[n * TSTRIDE + kc + 4];
                bl[nt][0] = Bls[n * TSTRIDE + kc];
                bl[nt][1] = Bls[n * TSTRIDE + kc + 4];
            }
#pragma unroll
            for (int mt = 0; mt < 2; mt++)
#pragma unroll
                for (int nt = 0; nt < 8; nt++) {
                    mma_tf32(acc[mt][nt], ah[mt][0], ah[mt][1], ah[mt][2], ah[mt][3],
                             bh[nt][0], bh[nt][1]);
                    mma_tf32(acc[mt][nt], ah[mt][0], ah[mt][1], ah[mt][2], ah[mt][3],
                             bl[nt][0], bl[nt][1]);
                    mma_tf32(acc[mt][nt], al[mt][0], al[mt][1], al[mt][2], al[mt][3],
                             bh[nt][0], bh[nt][1]);
                }
        }
        __syncthreads();
        if (++bufi == 3) bufi = 0;
    }

#pragma unroll
    for (int mt = 0; mt < 2; mt++) {
        const int r = m0 + wm * 32 + mt * 16 + lr;
#pragma unroll
        for (int nt = 0; nt < 8; nt++) {
            const int cN = n0 + wn * 64 + nt * 8 + 2 * lc;
            *(float2*)(Cp + (size_t)r * N + cN) =
                make_float2(acc[mt][nt][0], acc[mt][nt][1]);
            *(float2*)(Cp + (size_t)(r + 8) * N + cN) =
                make_float2(acc[mt][nt][2], acc[mt][nt][3]);
        }
    }
}

// ============================================================
// fused RMS kernels
// ============================================================
__device__ __forceinline__ void rms_row(float* row, const float* g, int C,
                                        const float* mean, int tid)
{
    float vr[4];
    int cnt = C >> 7;        // 1 or 4
    float ss = 0.f;
#pragma unroll 4
    for (int j = 0; j < cnt; j++) {
        int i = tid + j * 128;
        float v = row[i];
        if (mean) v += GAINc * mean[i & 31];
        vr[j] = v;
        ss += v * v;
    }
#pragma unroll
    for (int o = 16; o; o >>= 1) ss += __shfl_xor_sync(~0u, ss, o);
    __shared__ float ws[4];
    if ((tid & 31) == 0) ws[tid >> 5] = ss;
    __syncthreads();
    float tot = ws[0] + ws[1] + ws[2] + ws[3];
    float r = rsqrtf(tot / (float)C + EPSc);
#pragma unroll 4
    for (int j = 0; j < cnt; j++) {
        int i = tid + j * 128;
        row[i] = vr[j] * r * g[i];
    }
}

// three tensors in one launch (no mean)
__global__ void __launch_bounds__(128) rms3(
    float* pa, const float* ga, int Ca,
    float* pb, const float* gb, int Cb,
    float* pc, const float* gc, int Cc)
{
    int t = blockIdx.x;
    if (t < Tc)            rms_row(pa + (size_t)t * Ca, ga, Ca, nullptr, threadIdx.x);
    else if (t < 2 * Tc)   rms_row(pb + (size_t)(t - Tc) * Cb, gb, Cb, nullptr, threadIdx.x);
    else                   rms_row(pc + (size_t)(t - 2 * Tc) * Cc, gc, Cc, nullptr, threadIdx.x);
}

// two tensors in one launch, optional per-token mean add
__global__ void __launch_bounds__(128) rms2(
    float* pa, const float* ga, int Ca, const float* ma,
    float* pb, const float* gb, int Cb, const float* mb)
{
    int t = blockIdx.x;
    if (t < Tc) rms_row(pa + (size_t)t * Ca, ga, Ca, ma ? ma + (size_t)t * 32 : nullptr, threadIdx.x);
    else {
        t -= Tc;
        rms_row(pb + (size_t)t * Cb, gb, Cb, mb ? mb + (size_t)t * 32 : nullptr, threadIdx.x);
    }
}

// rms for pre-out (C=512) writing tf32 hi/lo split (for out-proj GEMM)
__global__ void __launch_bounds__(128) rms_split(
    const float* __restrict__ x, const float* __restrict__ g,
    float* __restrict__ hi, float* __restrict__ lo)
{
    const int t = blockIdx.x;
    const float* row = x + (size_t)t * LATc;
    const int tid = threadIdx.x;
    float vr[4];
    float ss = 0.f;
#pragma unroll
    for (int j = 0; j < 4; j++) {
        float v = row[tid + j * 128];
        vr[j] = v;
        ss += v * v;
    }
#pragma unroll
    for (int o = 16; o; o >>= 1) ss += __shfl_xor_sync(~0u, ss, o);
    __shared__ float ws[4];
    if ((tid & 31) == 0) ws[tid >> 5] = ss;
    __syncthreads();
    float tot = ws[0] + ws[1] + ws[2] + ws[3];
    float r = rsqrtf(tot / (float)LATc + EPSc);
#pragma unroll
    for (int j = 0; j < 4; j++) {
        int i = tid + j * 128;
        float y = vr[j] * r * g[i];
        float h, l;
        split_tf32(y, h, l);
        hi[(size_t)t * LATc + i] = h;
        lo[(size_t)t * LATc + i] = l;
    }
}

// ============================================================
// Grouped causal conv (tiled), K=3, 32 ch/group
// ============================================================
__global__ void __launch_bounds__(256) conv_causal_t(
    float* __restrict__ y, const float* __restrict__ x,
    const float* __restrict__ w, int C)
{
    __shared__ float ws[96][33];
    __shared__ float xs[66][32];
    const int tid = threadIdx.x;
    const int t0 = blockIdx.x * 64;
    const int base = blockIdx.y * 32;
    const int s0 = t0 & (Sc - 1);

    for (int idx = tid; idx < 3072; idx += 256) {
        int co = idx / 96;
        int r = idx - co * 96;
        ws[r][co] = w[(size_t)(base + co) * 96 + r];
    }
    for (int idx = tid; idx < 66 * 32; idx += 256) {
        int row = idx >> 5;
        int ci = idx & 31;
        int srow = s0 - 2 + row;
        xs[row][ci] = (srow >= 0 && row < 66)
            ? x[(size_t)(t0 - 2 + row) * C + base + ci] : 0.f;
    }
    __syncthreads();

    const int co = tid & 31;
    const int tg = tid >> 5;
#pragma unroll
    for (int tk = 0; tk < 8; tk++) {
        const int tt = tg * 8 + tk;
        float acc = 0.f;
#pragma unroll 8
        for (int ci = 0; ci < 32; ci++) {
#pragma unroll
            for (int j = 0; j < 3; j++)
                acc += ws[ci * 3 + j][co] * xs[tt + j][ci];
        }
        y[(size_t)(t0 + tt) * C + base + co] = acc;
    }
}

// ============================================================
// Per-token head-mean
// ============================================================
__global__ void __launch_bounds__(256) head_mean(
    float* __restrict__ out, const float* __restrict__ x, int C, int heads)
{
    const int idx = blockIdx.x * 256 + threadIdx.x;
    if (idx >= Tc * HDc) return;
    const int t = idx >> 5;
    const int d = idx & 31;
    const float* row = x + (size_t)t * C + d;
    float s = 0.f;
    for (int h = 0; h < heads; h++) s += row[h * 32];
    out[idx] = s / (float)heads;
}

// ============================================================
// merged q+k per-head L2 norm + RoPE
// ============================================================
__global__ void __launch_bounds__(128) headnorm_rope2(
    float* __restrict__ xq, float* __restrict__ xk,
    const float* __restrict__ key_temp)
{
    const int idx = blockIdx.x * 128 + threadIdx.x;
    float* p;
    int s, is_k;
    if (idx < Tc * NHc) {
        int t = idx >> 4;
        int h = idx & 15;
        p = xq + (size_t)t * LATc + h * 32;
        s = t & (Sc - 1);
        is_k = 0;
    } else {
        int j = idx - Tc * NHc;
        int t = j >> 2;
        int h = j & 3;
        p = xk + (size_t)t * KVDc + h * 32;
        s = t & (Sc - 1);
        is_k = 1;
    }
    float v[32];
    float ss = 0.f;
#pragma unroll
    for (int d = 0; d < 32; d++) { v[d] = p[d]; ss += v[d] * v[d]; }
    float n = fmaxf(sqrtf(ss), 1e-12f);
    float f = is_k ? (5.656854249492380f * key_temp[0] / n) : (1.0f / n);
#pragma unroll
    for (int d = 0; d < 32; d++) v[d] *= f;
#pragma unroll
    for (int i = 0; i < 16; i++) {
        float fr = expf(-(float)i * 0.575646273248511f);
        float ang = (float)s * fr;
        float sn, cs;
        sincosf(ang, &sn, &cs);
        float x1 = v[2 * i], x2 = v[2 * i + 1];
        v[2 * i]     = x1 * cs - x2 * sn;
        v[2 * i + 1] = x1 * sn + x2 * cs;
    }
#pragma unroll
    for (int d = 0; d < 32; d++) p[d] = v[d];
}

// ============================================================
// Flash-style causal attention (GQA 16 q-heads -> 4 kv-heads)
// ============================================================
__global__ void __launch_bounds__(128) flash_attn(
    float* __restrict__ o, const float* __restrict__ q,
    const float* __restrict__ k, const float* __restrict__ v)
{
    __shared__ float4 Ks[32][8];
    __shared__ float4 Vs[32][8];
    const int bh = blockIdx.y;
    const int b = bh / NHc;
    const int h = bh - b * NHc;
    const int kh = h >> 2;
    const int tid = threadIdx.x;
    const int sq = blockIdx.x * 128 + tid;

    float4 q4[8];
    {
        const float4* qp = (const float4*)(q + (size_t)(b * Sc + sq) * LATc + h * 32);
#pragma unroll
        for (int d = 0; d < 8; d++) q4[d] = qp[d];
    }
    float4 oa[8];
#pragma unroll
    for (int d = 0; d < 8; d++) oa[d] = make_float4(0.f, 0.f, 0.f, 0.f);
    float m = -1e30f, l = 0.f;

    const int maxs = blockIdx.x * 128 + 127;
    const int ntiles = (maxs >> 5) + 1;

    for (int jt = 0; jt < ntiles; jt++) {
        const int j0 = jt << 5;
        __syncthreads();
        for (int u = tid; u < 256; u += 128) {
            int jj = u >> 3, d = u & 7;
            size_t gi = (size_t)(b * Sc + j0 + jj) * KVDc + kh * 32 + d * 4;
            Ks[jj][d] = *(const float4*)(k + gi);
            Vs[jj][d] = *(const float4*)(v + gi);
        }
        __syncthreads();
        if (j0 <= sq) {
            const bool full = (j0 + 31) <= sq;
            float sc[32];
#pragma unroll
            for (int j = 0; j < 32; j++) {
                float s = 0.f;
#pragma unroll
                for (int d = 0; d < 8; d++) {
                    float4 kv = Ks[j][d];
                    s += q4[d].x * kv.x + q4[d].y * kv.y
                       + q4[d].z * kv.z + q4[d].w * kv.w;
                }
                sc[j] = s;
            }
            if (!full) {
#pragma unroll
                for (int j = 0; j < 32; j++)
                    if (j0 + j > sq) sc[j] = -1e30f;
            }
            float tm = m;
#pragma unroll
            for (int j = 0; j < 32; j++) tm = fmaxf(tm, sc[j]);
            float alpha = __expf(m - tm);
            m = tm;
            l *= alpha;
#pragma unroll
            for (int d = 0; d < 8; d++) {
                oa[d].x *= alpha; oa[d].y *= alpha;
                oa[d].z *= alpha; oa[d].w *= alpha;
            }
#pragma unroll
            for (int j = 0; j < 32; j++) {
                float p = __expf(sc[j] - m);
                l += p;
#pragma unroll
                for (int d = 0; d < 8; d++) {
                    float4 vv = Vs[j][d];
                    oa[d].x += p * vv.x; oa[d].y += p * vv.y;
                    oa[d].z += p * vv.z; oa[d].w += p * vv.w;
                }
            }
        }
    }

    float inv = 1.0f / l;
    float4* op = (float4*)(o + (size_t)(b * Sc + sq) * LATc + h * 32);
#pragma unroll
    for (int d = 0; d < 8; d++) {
        op[d] = make_float4(oa[d].x * inv, oa[d].y * inv,
                            oa[d].z * inv, oa[d].w * inv);
    }
}

// ============================================================
// host launcher
// ============================================================
extern "C" void kernel_launch(void* const* d_in, const int* in_sizes, int n_in,
                              void* d_out, int out_size)
{
    const float* x        = (const float*)d_in[0];
    const float* w_q      = (const float*)d_in[1];
    const float* w_k      = (const float*)d_in[2];
    const float* w_v      = (const float*)d_in[3];
    const float* g_latent = (const float*)d_in[4];
    const float* g_kv     = (const float*)d_in[5];
    const float* conv_q_w = (const float*)d_in[6];
    const float* conv_k_w = (const float*)d_in[7];
    const float* g_conv   = (const float*)d_in[8];
    const float* g_kconv  = (const float*)d_in[9];
    const float* g_postq  = (const float*)d_in[10];
    const float* g_postk  = (const float*)d_in[11];
    const float* key_temp = (const float*)d_in[12];
    const float* g_preout = (const float*)d_in[13];
    const float* w_o      = (const float*)d_in[14];
    float* out = (float*)d_out;

    float *pq, *pk, *pv, *pqc, *pkc, *pqm, *pkm, *po;
    float *pxh, *pxl, *pwh, *pwl, *pph, *ppl;
    cudaGetSymbolAddress((void**)&pq,  g_q);
    cudaGetSymbolAddress((void**)&pk,  g_k);
    cudaGetSymbolAddress((void**)&pv,  g_v);
    cudaGetSymbolAddress((void**)&pqc, g_qc);
    cudaGetSymbolAddress((void**)&pkc, g_kc);
    cudaGetSymbolAddress((void**)&pqm, g_qm);
    cudaGetSymbolAddress((void**)&pkm, g_km);
    cudaGetSymbolAddress((void**)&po,  g_o);
    cudaGetSymbolAddress((void**)&pxh, g_xh);
    cudaGetSymbolAddress((void**)&pxl, g_xl);
    cudaGetSymbolAddress((void**)&pwh, g_wh);
    cudaGetSymbolAddress((void**)&pwl, g_wl);
    cudaGetSymbolAddress((void**)&pph, g_ph);
    cudaGetSymbolAddress((void**)&ppl, g_pl);

    cudaFuncSetAttribute(gemm_pre, cudaFuncAttributeMaxDynamicSharedMemorySize, GEMM_SMEM);

    // 0) pre-split x and weights into tf32 hi/lo
    split_arr<<<(Tc * Dc / 4 + 255) / 256, 256>>>(pxh, pxl, x, Tc * Dc / 4);
    split_arr<<<(LATc * Dc / 4 + 255) / 256, 256>>>(pwh + OFF_WQ, pwl + OFF_WQ, w_q, LATc * Dc / 4);
    split_arr<<<(KVDc * Dc / 4 + 255) / 256, 256>>>(pwh + OFF_WK, pwl + OFF_WK, w_k, KVDc * Dc / 4);
    split_arr<<<(KVDc * Dc / 4 + 255) / 256, 256>>>(pwh + OFF_WV, pwl + OFF_WV, w_v, KVDc * Dc / 4);
    split_arr<<<(Dc * LATc / 4 + 255) / 256, 256>>>(pwh + OFF_WO, pwl + OFF_WO, w_o, Dc * LATc / 4);

    // 1) fused q/k/v projections
    gemm_pre<<<dim3(6, Tc / 128), 256, GEMM_SMEM>>>(
        pxh, pxl, Dc, pwh, pwl,
        OFF_WQ, pq, 4, LATc, OFF_WK, pk, OFF_WV, pv);

    // 2) first RMS norms (one launch)
    rms3<<<3 * Tc, 128>>>(pq, g_latent, LATc, pk, g_kv, KVDc, pv, g_kv, KVDc);

    // 3) causal grouped conv + RMS (one launch)
    conv_causal_t<<<dim3(Tc / 64, LATc / 32), 256>>>(pqc, pq, conv_q_w, LATc);
    conv_causal_t<<<dim3(Tc / 64, KVDc / 32), 256>>>(pkc, pk, conv_k_w, KVDc);
    rms2<<<2 * Tc, 128>>>(pqc, g_conv, LATc, nullptr, pkc, g_kconv, KVDc, nullptr);

    // 4) cross-coupling means + post RMS (mean-add fused into rms)
    head_mean<<<(Tc * HDc) / 256, 256>>>(pqm, pq, LATc, NHc);
    head_mean<<<(Tc * HDc) / 256, 256>>>(pkm, pk, KVDc, NKVc);
    rms2<<<2 * Tc, 128>>>(pqc, g_postq, LATc, pkm, pkc, g_postk, KVDc, pqm);

    // 5) per-head L2 norm + RoPE (merged q+k)
    headnorm_rope2<<<(Tc * (NHc + NKVc)) / 128, 128>>>(pqc, pkc, key_temp);

    // 6) causal attention
    flash_attn<<<dim3(Sc / 128, Bc * NHc), 128>>>(po, pqc, pkc, pv);

    // 7) pre-out RMS fused with tf32 split, then output projection
    rms_split<<<Tc, 128>>>(po, g_preout, pph, ppl);
    gemm_pre<<<dim3(16, Tc / 128), 256, GEMM_SMEM>>>(
        pph, ppl, LATc, pwh, pwl,
        OFF_WO, out, 16, Dc, 0, nullptr, 0, nullptr);
}

// round 6
// speedup vs baseline: 1.2791x; 1.2791x over previous
#include <cuda_runtime.h>
#include <cuda_bf16.h>
#include <math.h>
#include <cstdint>

#define Bc   4
#define Sc   2048
#define Dc   2048
#define LATc 512
#define NHc  16
#define NKVc 4
#define HDc  32
#define KVDc 128
#define Tc   (Bc * Sc)
#define GAINc 0.25f
#define EPSc  1e-6f

// weight offsets inside the packed split-weight arrays
#define OFF_WQ 0
#define OFF_WK (LATc * Dc)
#define OFF_WV (OFF_WK + KVDc * Dc)
#define OFF_WO (OFF_WV + KVDc * Dc)
#define WTOT   (OFF_WO + Dc * LATc)

// -------- scratch (device globals; no allocation allowed) --------
__device__ float g_q [Tc * LATc];
__device__ float g_k [Tc * KVDc];
__device__ float g_v [Tc * KVDc];
__device__ float g_qc[Tc * LATc];
__device__ float g_kc[Tc * KVDc];
__device__ float g_qm[Tc * HDc];
__device__ float g_km[Tc * HDc];
__device__ float g_o [Tc * LATc];
__device__ __nv_bfloat16 gb_xh[Tc * Dc];
__device__ __nv_bfloat16 gb_xl[Tc * Dc];
__device__ __nv_bfloat16 gb_wh[WTOT];
__device__ __nv_bfloat16 gb_wl[WTOT];
__device__ __nv_bfloat16 gb_ph[Tc * LATc];
__device__ __nv_bfloat16 gb_pl[Tc * LATc];

// ---------------- helpers ----------------
__device__ __forceinline__ void mma_bf16(float* d, uint32_t a0, uint32_t a1,
                                         uint32_t a2, uint32_t a3,
                                         uint32_t b0, uint32_t b1) {
    asm volatile(
        "mma.sync.aligned.m16n8k16.row.col.f32.bf16.bf16.f32 "
        "{%0,%1,%2,%3}, {%4,%5,%6,%7}, {%8,%9}, {%0,%1,%2,%3};"
        : "+f"(d[0]), "+f"(d[1]), "+f"(d[2]), "+f"(d[3])
        : "r"(a0), "r"(a1), "r"(a2), "r"(a3), "r"(b0), "r"(b1));
}
__device__ __forceinline__ void fsplit_bf16(float x, __nv_bfloat16& h, __nv_bfloat16& l) {
    h = __float2bfloat16_rn(x);
    l = __float2bfloat16_rn(x - __bfloat162float(h));
}
__device__ __forceinline__ uint32_t smem_u32(const void* p) {
    uint32_t a;
    asm("{ .reg .u64 t; cvta.to.shared.u64 t, %1; cvt.u32.u64 %0, t; }" : "=r"(a) : "l"(p));
    return a;
}
#define CP_ASYNC16(dst, src) \
    asm volatile("cp.async.cg.shared.global [%0], [%1], 16;" :: "r"(dst), "l"(src))
#define CP_COMMIT() asm volatile("cp.async.commit_group;" ::: "memory")
#define CP_WAIT(n)  asm volatile("cp.async.wait_group %0;" :: "n"(n) : "memory")

// ============================================================
// split float array into bf16 hi/lo (vectorized)
// ============================================================
__global__ void __launch_bounds__(256) split_arr(
    __nv_bfloat16* __restrict__ hi, __nv_bfloat16* __restrict__ lo,
    const float* __restrict__ src, int n4)
{
    int i = blockIdx.x * 256 + threadIdx.x;
    if (i >= n4) return;
    float4 v = ((const float4*)src)[i];
    __nv_bfloat16 h[4], l[4];
    fsplit_bf16(v.x, h[0], l[0]);
    fsplit_bf16(v.y, h[1], l[1]);
    fsplit_bf16(v.z, h[2], l[2]);
    fsplit_bf16(v.w, h[3], l[3]);
    ((uint2*)hi)[i] = *(uint2*)h;
    ((uint2*)lo)[i] = *(uint2*)l;
}

// ============================================================
// bf16 3-term split GEMM via mma.sync.m16n8k16:
// C[M,N] = A[M,K]*B[N,K]^T, fp32 out. 128x128 tile, K-chunk 64, 3 stages.
// ============================================================
#define TSTRIDE 36                        // uint32 per smem row (64 bf16 data + pad)
#define ABYTES  (128 * TSTRIDE * 4)       // 18432
#define SBYTES  (4 * ABYTES)              // Ah, Al, Bh, Bl per stage
#define GEMM_SMEM (3 * SBYTES)            // 221184 B

__global__ void __launch_bounds__(256, 1) gemm_bf16(
    const __nv_bfloat16* __restrict__ Ah, const __nv_bfloat16* __restrict__ Al, int K,
    const __nv_bfloat16* __restrict__ Wh, const __nv_bfloat16* __restrict__ Wl,
    size_t off0, float* __restrict__ C0, int nx0, int N0,
    size_t off1, float* __restrict__ C1,
    size_t off2, float* __restrict__ C2)
{
    extern __shared__ char sm[];
    const int tid = threadIdx.x;
    const int wid = tid >> 5;
    const int lane = tid & 31;
    const int lr = lane >> 2;
    const int lc = lane & 3;
    const int wm = wid & 3;
    const int wn = wid >> 2;

    int bx = blockIdx.x;
    size_t woff;
    float* Cp;
    int N;
    if (bx < nx0)       { woff = off0; Cp = C0; N = N0; }
    else if (bx == nx0) { woff = off1; Cp = C1; N = 128; bx = 0; }
    else                { woff = off2; Cp = C2; N = 128; bx = 0; }
    const __nv_bfloat16* Bh = Wh + woff;
    const __nv_bfloat16* Bl = Wl + woff;
    const int m0 = blockIdx.y * 128;
    const int n0 = bx * 128;
    const int NC = K >> 6;                // 64 bf16 per chunk

    const uint32_t smb = smem_u32(sm);
    int grow[4], gc16[4];
    uint32_t sdst[4];
#pragma unroll
    for (int j = 0; j < 4; j++) {
        int seg = tid + j * 256;          // 1024 segs per part
        grow[j] = seg >> 3;
        gc16[j] = seg & 7;
        sdst[j] = (uint32_t)(grow[j] * (TSTRIDE * 4) + gc16[j] * 16);
    }

    float acc[2][8][4];
#pragma unroll
    for (int mt = 0; mt < 2; mt++)
#pragma unroll
        for (int nt = 0; nt < 8; nt++)
#pragma unroll
            for (int c = 0; c < 4; c++) acc[mt][nt][c] = 0.f;

    // prefetch chunks 0, 1
#pragma unroll
    for (int pc = 0; pc < 2; pc++) {
        const uint32_t so = smb + (uint32_t)pc * SBYTES;
        const int kt = pc << 6;
#pragma unroll
        for (int j = 0; j < 4; j++) {
            size_t ao = (size_t)(m0 + grow[j]) * K + kt + gc16[j] * 8;
            size_t bo = (size_t)(n0 + grow[j]) * K + kt + gc16[j] * 8;
            CP_ASYNC16(so + sdst[j],              Ah + ao);
            CP_ASYNC16(so + ABYTES + sdst[j],     Al + ao);
            CP_ASYNC16(so + 2 * ABYTES + sdst[j], Bh + bo);
            CP_ASYNC16(so + 3 * ABYTES + sdst[j], Bl + bo);
        }
        CP_COMMIT();
    }

    int bufi = 0;
    for (int i = 0; i < NC; i++) {
        if (i + 2 < NC) {
            int dsti = bufi + 2; if (dsti >= 3) dsti -= 3;
            const uint32_t so = smb + (uint32_t)dsti * SBYTES;
            const int kt = (i + 2) << 6;
#pragma unroll
            for (int j = 0; j < 4; j++) {
                size_t ao = (size_t)(m0 + grow[j]) * K + kt + gc16[j] * 8;
                size_t bo = (size_t)(n0 + grow[j]) * K + kt + gc16[j] * 8;
                CP_ASYNC16(so + sdst[j],              Ah + ao);
                CP_ASYNC16(so + ABYTES + sdst[j],     Al + ao);
                CP_ASYNC16(so + 2 * ABYTES + sdst[j], Bh + bo);
                CP_ASYNC16(so + 3 * ABYTES + sdst[j], Bl + bo);
            }
        }
        CP_COMMIT();
        CP_WAIT(2);
        __syncthreads();

        const uint32_t* Ahs = (const uint32_t*)(sm + (size_t)bufi * SBYTES);
        const uint32_t* Als = (const uint32_t*)(sm + (size_t)bufi * SBYTES + ABYTES);
        const uint32_t* Bhs = (const uint32_t*)(sm + (size_t)bufi * SBYTES + 2 * ABYTES);
        const uint32_t* Bls = (const uint32_t*)(sm + (size_t)bufi * SBYTES + 3 * ABYTES);

#pragma unroll
        for (int ks = 0; ks < 4; ks++) {          // 4 x K=16 per chunk
            const int kc = ks * 8 + lc;
            uint32_t ah[2][4], al[2][4];
#pragma unroll
            for (int mt = 0; mt < 2; mt++) {
                const int r = wm * 32 + mt * 16 + lr;
                ah[mt][0] = Ahs[r * TSTRIDE + kc];
                ah[mt][1] = Ahs[(r + 8) * TSTRIDE + kc];
                ah[mt][2] = Ahs[r * TSTRIDE + kc + 4];
                ah[mt][3] = Ahs[(r + 8) * TSTRIDE + kc + 4];
                al[mt][0] = Als[r * TSTRIDE + kc];
                al[mt][1] = Als[(r + 8) * TSTRIDE + kc];
                al[mt][2] = Als[r * TSTRIDE + kc + 4];
                al[mt][3] = Als[(r + 8) * TSTRIDE + kc + 4];
            }
            uint32_t bh[8][2], bl[8][2];
#pragma unroll
            for (int nt = 0; nt < 8; nt++) {
                const int n = wn * 64 + nt * 8 + lr;
                bh[nt][0] = Bhs[n * TSTRIDE + kc];
                bh[nt][1] = Bhs[n * TSTRIDE + kc + 4];
                bl[nt][0] = Bls[n * TSTRIDE + kc];
                bl[nt][1] = Bls[n * TSTRIDE + kc + 4];
            }
#pragma unroll
            for (int mt = 0; mt < 2; mt++)
#pragma unroll
                for (int nt = 0; nt < 8; nt++) {
                    mma_bf16(acc[mt][nt], ah[mt][0], ah[mt][1], ah[mt][2], ah[mt][3],
                             bh[nt][0], bh[nt][1]);
                    mma_bf16(acc[mt][nt], ah[mt][0], ah[mt][1], ah[mt][2], ah[mt][3],
                             bl[nt][0], bl[nt][1]);
                    mma_bf16(acc[mt][nt], al[mt][0], al[mt][1], al[mt][2], al[mt][3],
                             bh[nt][0], bh[nt][1]);
                }
        }
        __syncthreads();
        if (++bufi == 3) bufi = 0;
    }

#pragma unroll
    for (int mt = 0; mt < 2; mt++) {
        const int r = m0 + wm * 32 + mt * 16 + lr;
#pragma unroll
        for (int nt = 0; nt < 8; nt++) {
            const int cN = n0 + wn * 64 + nt * 8 + 2 * lc;
            *(float2*)(Cp + (size_t)r * N + cN) =
                make_float2(acc[mt][nt][0], acc[mt][nt][1]);
            *(float2*)(Cp + (size_t)(r + 8) * N + cN) =
                make_float2(acc[mt][nt][2], acc[mt][nt][3]);
        }
    }
}

// ============================================================
// fused RMS kernels
// ============================================================
__device__ __forceinline__ void rms_row(float* row, const float* g, int C,
                                        const float* mean, int tid)
{
    float vr[4];
    int cnt = C >> 7;
    float ss = 0.f;
#pragma unroll 4
    for (int j = 0; j < cnt; j++) {
        int i = tid + j * 128;
        float v = row[i];
        if (mean) v += GAINc * mean[i & 31];
        vr[j] = v;
        ss += v * v;
    }
#pragma unroll
    for (int o = 16; o; o >>= 1) ss += __shfl_xor_sync(~0u, ss, o);
    __shared__ float ws[4];
    if ((tid & 31) == 0) ws[tid >> 5] = ss;
    __syncthreads();
    float tot = ws[0] + ws[1] + ws[2] + ws[3];
    float r = rsqrtf(tot / (float)C + EPSc);
#pragma unroll 4
    for (int j = 0; j < cnt; j++) {
        int i = tid + j * 128;
        row[i] = vr[j] * r * g[i];
    }
}

__global__ void __launch_bounds__(128) rms3(
    float* pa, const float* ga, int Ca,
    float* pb, const float* gb, int Cb,
    float* pc, const float* gc, int Cc)
{
    int t = blockIdx.x;
    if (t < Tc)          rms_row(pa + (size_t)t * Ca, ga, Ca, nullptr, threadIdx.x);
    else if (t < 2 * Tc) rms_row(pb + (size_t)(t - Tc) * Cb, gb, Cb, nullptr, threadIdx.x);
    else                 rms_row(pc + (size_t)(t - 2 * Tc) * Cc, gc, Cc, nullptr, threadIdx.x);
}

__global__ void __launch_bounds__(128) rms2(
    float* pa, const float* ga, int Ca, const float* ma,
    float* pb, const float* gb, int Cb, const float* mb)
{
    int t = blockIdx.x;
    if (t < Tc) rms_row(pa + (size_t)t * Ca, ga, Ca, ma ? ma + (size_t)t * 32 : nullptr, threadIdx.x);
    else {
        t -= Tc;
        rms_row(pb + (size_t)t * Cb, gb, Cb, mb ? mb + (size_t)t * 32 : nullptr, threadIdx.x);
    }
}

// rms for pre-out (C=512) writing bf16 hi/lo split (for out-proj GEMM)
__global__ void __launch_bounds__(128) rms_split(
    const float* __restrict__ x, const float* __restrict__ g,
    __nv_bfloat16* __restrict__ hi, __nv_bfloat16* __restrict__ lo)
{
    const int t = blockIdx.x;
    const float* row = x + (size_t)t * LATc;
    const int tid = threadIdx.x;
    float vr[4];
    float ss = 0.f;
#pragma unroll
    for (int j = 0; j < 4; j++) {
        float v = row[tid + j * 128];
        vr[j] = v;
        ss += v * v;
    }
#pragma unroll
    for (int o = 16; o; o >>= 1) ss += __shfl_xor_sync(~0u, ss, o);
    __shared__ float ws[4];
    if ((tid & 31) == 0) ws[tid >> 5] = ss;
    __syncthreads();
    float tot = ws[0] + ws[1] + ws[2] + ws[3];
    float r = rsqrtf(tot / (float)LATc + EPSc);
#pragma unroll
    for (int j = 0; j < 4; j++) {
        int i = tid + j * 128;
        float y = vr[j] * r * g[i];
        __nv_bfloat16 h, l;
        fsplit_bf16(y, h, l);
        hi[(size_t)t * LATc + i] = h;
        lo[(size_t)t * LATc + i] = l;
    }
}

// ============================================================
// Grouped causal conv (tiled), K=3, 32 ch/group
// ============================================================
__global__ void __launch_bounds__(256) conv_causal_t(
    float* __restrict__ y, const float* __restrict__ x,
    const float* __restrict__ w, int C)
{
    __shared__ float ws[96][33];
    __shared__ float xs[66][32];
    const int tid = threadIdx.x;
    const int t0 = blockIdx.x * 64;
    const int base = blockIdx.y * 32;
    const int s0 = t0 & (Sc - 1);

    for (int idx = tid; idx < 3072; idx += 256) {
        int co = idx / 96;
        int r = idx - co * 96;
        ws[r][co] = w[(size_t)(base + co) * 96 + r];
    }
    for (int idx = tid; idx < 66 * 32; idx += 256) {
        int row = idx >> 5;
        int ci = idx & 31;
        int srow = s0 - 2 + row;
        xs[row][ci] = (srow >= 0 && row < 66)
            ? x[(size_t)(t0 - 2 + row) * C + base + ci] : 0.f;
    }
    __syncthreads();

    const int co = tid & 31;
    const int tg = tid >> 5;
#pragma unroll
    for (int tk = 0; tk < 8; tk++) {
        const int tt = tg * 8 + tk;
        float acc = 0.f;
#pragma unroll 8
        for (int ci = 0; ci < 32; ci++) {
#pragma unroll
            for (int j = 0; j < 3; j++)
                acc += ws[ci * 3 + j][co] * xs[tt + j][ci];
        }
        y[(size_t)(t0 + tt) * C + base + co] = acc;
    }
}

// ============================================================
// Per-token head-mean
// ============================================================
__global__ void __launch_bounds__(256) head_mean(
    float* __restrict__ out, const float* __restrict__ x, int C, int heads)
{
    const int idx = blockIdx.x * 256 + threadIdx.x;
    if (idx >= Tc * HDc) return;
    const int t = idx >> 5;
    const int d = idx & 31;
    const float* row = x + (size_t)t * C + d;
    float s = 0.f;
    for (int h = 0; h < heads; h++) s += row[h * 32];
    out[idx] = s / (float)heads;
}

// ============================================================
// merged q+k per-head L2 norm + RoPE
// ============================================================
__global__ void __launch_bounds__(128) headnorm_rope2(
    float* __restrict__ xq, float* __restrict__ xk,
    const float* __restrict__ key_temp)
{
    const int idx = blockIdx.x * 128 + threadIdx.x;
    float* p;
    int s, is_k;
    if (idx < Tc * NHc) {
        int t = idx >> 4;
        int h = idx & 15;
        p = xq + (size_t)t * LATc + h * 32;
        s = t & (Sc - 1);
        is_k = 0;
    } else {
        int j = idx - Tc * NHc;
        int t = j >> 2;
        int h = j & 3;
        p = xk + (size_t)t * KVDc + h * 32;
        s = t & (Sc - 1);
        is_k = 1;
    }
    float v[32];
    float ss = 0.f;
#pragma unroll
    for (int d = 0; d < 32; d++) { v[d] = p[d]; ss += v[d] * v[d]; }
    float n = fmaxf(sqrtf(ss), 1e-12f);
    float f = is_k ? (5.656854249492380f * key_temp[0] / n) : (1.0f / n);
#pragma unroll
    for (int d = 0; d < 32; d++) v[d] *= f;
#pragma unroll
    for (int i = 0; i < 16; i++) {
        float fr = expf(-(float)i * 0.575646273248511f);
        float ang = (float)s * fr;
        float sn, cs;
        sincosf(ang, &sn, &cs);
        float x1 = v[2 * i], x2 = v[2 * i + 1];
        v[2 * i]     = x1 * cs - x2 * sn;
        v[2 * i + 1] = x1 * sn + x2 * cs;
    }
#pragma unroll
    for (int d = 0; d < 32; d++) p[d] = v[d];
}

// ============================================================
// Flash-style causal attention (GQA 16 q-heads -> 4 kv-heads)
// ============================================================
__global__ void __launch_bounds__(128) flash_attn(
    float* __restrict__ o, const float* __restrict__ q,
    const float* __restrict__ k, const float* __restrict__ v)
{
    __shared__ float4 Ks[32][8];
    __shared__ float4 Vs[32][8];
    const int bh = blockIdx.y;
    const int b = bh / NHc;
    const int h = bh - b * NHc;
    const int kh = h >> 2;
    const int tid = threadIdx.x;
    const int sq = blockIdx.x * 128 + tid;

    float4 q4[8];
    {
        const float4* qp = (const float4*)(q + (size_t)(b * Sc + sq) * LATc + h * 32);
#pragma unroll
        for (int d = 0; d < 8; d++) q4[d] = qp[d];
    }
    float4 oa[8];
#pragma unroll
    for (int d = 0; d < 8; d++) oa[d] = make_float4(0.f, 0.f, 0.f, 0.f);
    float m = -1e30f, l = 0.f;

    const int maxs = blockIdx.x * 128 + 127;
    const int ntiles = (maxs >> 5) + 1;

    for (int jt = 0; jt < ntiles; jt++) {
        const int j0 = jt << 5;
        __syncthreads();
        for (int u = tid; u < 256; u += 128) {
            int jj = u >> 3, d = u & 7;
            size_t gi = (size_t)(b * Sc + j0 + jj) * KVDc + kh * 32 + d * 4;
            Ks[jj][d] = *(const float4*)(k + gi);
            Vs[jj][d] = *(const float4*)(v + gi);
        }
        __syncthreads();
        if (j0 <= sq) {
            const bool full = (j0 + 31) <= sq;
            float sc[32];
#pragma unroll
            for (int j = 0; j < 32; j++) {
                float s = 0.f;
#pragma unroll
                for (int d = 0; d < 8; d++) {
                    float4 kv = Ks[j][d];
                    s += q4[d].x * kv.x + q4[d].y * kv.y
                       + q4[d].z * kv.z + q4[d].w * kv.w;
                }
                sc[j] = s;
            }
            if (!full) {
#pragma unroll
                for (int j = 0; j < 32; j++)
                    if (j0 + j > sq) sc[j] = -1e30f;
            }
            float tm = m;
#pragma unroll
            for (int j = 0; j < 32; j++) tm = fmaxf(tm, sc[j]);
            float alpha = __expf(m - tm);
            m = tm;
            l *= alpha;
#pragma unroll
            for (int d = 0; d < 8; d++) {
                oa[d].x *= alpha; oa[d].y *= alpha;
                oa[d].z *= alpha; oa[d].w *= alpha;
            }
#pragma unroll
            for (int j = 0; j < 32; j++) {
                float p = __expf(sc[j] - m);
                l += p;
#pragma unroll
                for (int d = 0; d < 8; d++) {
                    float4 vv = Vs[j][d];
                    oa[d].x += p * vv.x; oa[d].y += p * vv.y;
                    oa[d].z += p * vv.z; oa[d].w += p * vv.w;
                }
            }
        }
    }

    float inv = 1.0f / l;
    float4* op = (float4*)(o + (size_t)(b * Sc + sq) * LATc + h * 32);
#pragma unroll
    for (int d = 0; d < 8; d++) {
        op[d] = make_float4(oa[d].x * inv, oa[d].y * inv,
                            oa[d].z * inv, oa[d].w * inv);
    }
}

// ============================================================
// host launcher
// ============================================================
extern "C" void kernel_launch(void* const* d_in, const int* in_sizes, int n_in,
                              void* d_out, int out_size)
{
    const float* x        = (const float*)d_in[0];
    const float* w_q      = (const float*)d_in[1];
    const float* w_k      = (const float*)d_in[2];
    const float* w_v      = (const float*)d_in[3];
    const float* g_latent = (const float*)d_in[4];
    const float* g_kv     = (const float*)d_in[5];
    const float* conv_q_w = (const float*)d_in[6];
    const float* conv_k_w = (const float*)d_in[7];
    const float* g_conv   = (const float*)d_in[8];
    const float* g_kconv  = (const float*)d_in[9];
    const float* g_postq  = (const float*)d_in[10];
    const float* g_postk  = (const float*)d_in[11];
    const float* key_temp = (const float*)d_in[12];
    const float* g_preout = (const float*)d_in[13];
    const float* w_o      = (const float*)d_in[14];
    float* out = (float*)d_out;

    float *pq, *pk, *pv, *pqc, *pkc, *pqm, *pkm, *po;
    __nv_bfloat16 *pxh, *pxl, *pwh, *pwl, *pph, *ppl;
    cudaGetSymbolAddress((void**)&pq,  g_q);
    cudaGetSymbolAddress((void**)&pk,  g_k);
    cudaGetSymbolAddress((void**)&pv,  g_v);
    cudaGetSymbolAddress((void**)&pqc, g_qc);
    cudaGetSymbolAddress((void**)&pkc, g_kc);
    cudaGetSymbolAddress((void**)&pqm, g_qm);
    cudaGetSymbolAddress((void**)&pkm, g_km);
    cudaGetSymbolAddress((void**)&po,  g_o);
    cudaGetSymbolAddress((void**)&pxh, gb_xh);
    cudaGetSymbolAddress((void**)&pxl, gb_xl);
    cudaGetSymbolAddress((void**)&pwh, gb_wh);
    cudaGetSymbolAddress((void**)&pwl, gb_wl);
    cudaGetSymbolAddress((void**)&pph, gb_ph);
    cudaGetSymbolAddress((void**)&ppl, gb_pl);

    cudaFuncSetAttribute(gemm_bf16, cudaFuncAttributeMaxDynamicSharedMemorySize, GEMM_SMEM);

    // 0) pre-split x and weights into bf16 hi/lo
    split_arr<<<(Tc * Dc / 4 + 255) / 256, 256>>>(pxh, pxl, x, Tc * Dc / 4);
    split_arr<<<(LATc * Dc / 4 + 255) / 256, 256>>>(pwh + OFF_WQ, pwl + OFF_WQ, w_q, LATc * Dc / 4);
    split_arr<<<(KVDc * Dc / 4 + 255) / 256, 256>>>(pwh + OFF_WK, pwl + OFF_WK, w_k, KVDc * Dc / 4);
    split_arr<<<(KVDc * Dc / 4 + 255) / 256, 256>>>(pwh + OFF_WV, pwl + OFF_WV, w_v, KVDc * Dc / 4);
    split_arr<<<(Dc * LATc / 4 + 255) / 256, 256>>>(pwh + OFF_WO, pwl + OFF_WO, w_o, Dc * LATc / 4);

    // 1) fused q/k/v projections
    gemm_bf16<<<dim3(6, Tc / 128), 256, GEMM_SMEM>>>(
        pxh, pxl, Dc, pwh, pwl,
        OFF_WQ, pq, 4, LATc, OFF_WK, pk, OFF_WV, pv);

    // 2) first RMS norms (one launch)
    rms3<<<3 * Tc, 128>>>(pq, g_latent, LATc, pk, g_kv, KVDc, pv, g_kv, KVDc);

    // 3) causal grouped conv + RMS
    conv_causal_t<<<dim3(Tc / 64, LATc / 32), 256>>>(pqc, pq, conv_q_w, LATc);
    conv_causal_t<<<dim3(Tc / 64, KVDc / 32), 256>>>(pkc, pk, conv_k_w, KVDc);
    rms2<<<2 * Tc, 128>>>(pqc, g_conv, LATc, nullptr, pkc, g_kconv, KVDc, nullptr);

    // 4) cross-coupling means + post RMS (mean-add fused)
    head_mean<<<(Tc * HDc) / 256, 256>>>(pqm, pq, LATc, NHc);
    head_mean<<<(Tc * HDc) / 256, 256>>>(pkm, pk, KVDc, NKVc);
    rms2<<<2 * Tc, 128>>>(pqc, g_postq, LATc, pkm, pkc, g_postk, KVDc, pqm);

    // 5) per-head L2 norm + RoPE (merged q+k)
    headnorm_rope2<<<(Tc * (NHc + NKVc)) / 128, 128>>>(pqc, pkc, key_temp);

    // 6) causal attention
    flash_attn<<<dim3(Sc / 128, Bc * NHc), 128>>>(po, pqc, pkc, pv);

    // 7) pre-out RMS fused with bf16 split, then output projection
    rms_split<<<Tc, 128>>>(po, g_preout, pph, ppl);
    gemm_bf16<<<dim3(16, Tc / 128), 256, GEMM_SMEM>>>(
        pph, ppl, LATc, pwh, pwl,
        OFF_WO, out, 16, Dc, 0, nullptr, 0, nullptr);
}

// round 8
// speedup vs baseline: 1.9066x; 1.4905x over previous
#include <cuda_runtime.h>
#include <cuda_bf16.h>
#include <math.h>
#include <cstdint>

#define Bc   4
#define Sc   2048
#define Dc   2048
#define LATc 512
#define NHc  16
#define NKVc 4
#define HDc  32
#define KVDc 128
#define Tc   (Bc * Sc)
#define GAINc 0.25f
#define EPSc  1e-6f
#define L2E  1.4426950408889634f

// weight offsets inside the packed split-weight arrays
#define OFF_WQ 0
#define OFF_WK (LATc * Dc)
#define OFF_WV (OFF_WK + KVDc * Dc)
#define OFF_WO (OFF_WV + KVDc * Dc)
#define WTOT   (OFF_WO + Dc * LATc)

// -------- scratch (device globals; no allocation allowed) --------
__device__ float g_q [Tc * LATc];
__device__ float g_k [Tc * KVDc];
__device__ float g_v [Tc * KVDc];
__device__ float g_qc[Tc * LATc];
__device__ float g_kc[Tc * KVDc];
__device__ float g_qm[Tc * HDc];
__device__ float g_km[Tc * HDc];
__device__ float g_o [Tc * LATc];
__device__ __nv_bfloat16 gb_xh[Tc * Dc];
__device__ __nv_bfloat16 gb_xl[Tc * Dc];
__device__ __nv_bfloat16 gb_wh[WTOT];
__device__ __nv_bfloat16 gb_wl[WTOT];
__device__ __nv_bfloat16 gb_ph[Tc * LATc];
__device__ __nv_bfloat16 gb_pl[Tc * LATc];
__device__ __nv_bfloat16 gb_qh[Tc * LATc];
__device__ __nv_bfloat16 gb_ql[Tc * LATc];
__device__ __nv_bfloat16 gb_kh[Tc * KVDc];
__device__ __nv_bfloat16 gb_kl[Tc * KVDc];
__device__ __nv_bfloat16 gb_vth[Tc * KVDc];
__device__ __nv_bfloat16 gb_vtl[Tc * KVDc];

// ---------------- helpers ----------------
__device__ __forceinline__ void mma_bf16(float* d, uint32_t a0, uint32_t a1,
                                         uint32_t a2, uint32_t a3,
                                         uint32_t b0, uint32_t b1) {
    asm volatile(
        "mma.sync.aligned.m16n8k16.row.col.f32.bf16.bf16.f32 "
        "{%0,%1,%2,%3}, {%4,%5,%6,%7}, {%8,%9}, {%0,%1,%2,%3};"
        : "+f"(d[0]), "+f"(d[1]), "+f"(d[2]), "+f"(d[3])
        : "r"(a0), "r"(a1), "r"(a2), "r"(a3), "r"(b0), "r"(b1));
}
__device__ __forceinline__ void fsplit_bf16(float x, __nv_bfloat16& h, __nv_bfloat16& l) {
    h = __float2bfloat16_rn(x);
    l = __float2bfloat16_rn(x - __bfloat162float(h));
}
__device__ __forceinline__ uint32_t smem_u32(const void* p) {
    uint32_t a;
    asm("{ .reg .u64 t; cvta.to.shared.u64 t, %1; cvt.u32.u64 %0, t; }" : "=r"(a) : "l"(p));
    return a;
}
#define CP_ASYNC16(dst, src) \
    asm volatile("cp.async.cg.shared.global [%0], [%1], 16;" :: "r"(dst), "l"(src))
#define CP_ASYNC8(dst, src) \
    asm volatile("cp.async.ca.shared.global [%0], [%1], 8;" :: "r"(dst), "l"(src))
#define CP_COMMIT() asm volatile("cp.async.commit_group;" ::: "memory")
#define CP_WAIT(n)  asm volatile("cp.async.wait_group %0;" :: "n"(n) : "memory")

// exp2 without MUFU: degree-6 poly on fma pipe, exponent via bitfield
__device__ __forceinline__ float fexp2(float t) {
    t = fmaxf(t, -126.f);
    float fi = floorf(t);
    float f = t - fi;
    int i = (int)fi;
    float p = 1.5403530393381609e-4f;
    p = fmaf(p, f, 1.3333558146428443e-3f);
    p = fmaf(p, f, 9.6181291076284772e-3f);
    p = fmaf(p, f, 5.5504108664821580e-2f);
    p = fmaf(p, f, 2.4022650695910072e-1f);
    p = fmaf(p, f, 6.9314718055994531e-1f);
    p = fmaf(p, f, 1.0f);
    return p * __int_as_float((i + 127) << 23);
}
__device__ __forceinline__ void pack_split2(float a, float b, uint32_t& hi, uint32_t& lo) {
    __nv_bfloat16 ha = __float2bfloat16_rn(a);
    __nv_bfloat16 hb = __float2bfloat16_rn(b);
    __nv_bfloat16 la = __float2bfloat16_rn(a - __bfloat162float(ha));
    __nv_bfloat16 lb = __float2bfloat16_rn(b - __bfloat162float(hb));
    __nv_bfloat162 H; H.x = ha; H.y = hb;
    __nv_bfloat162 L; L.x = la; L.y = lb;
    hi = *(uint32_t*)&H; lo = *(uint32_t*)&L;
}

// ============================================================
// split float array into bf16 hi/lo (vectorized)
// ============================================================
__global__ void __launch_bounds__(256) split_arr(
    __nv_bfloat16* __restrict__ hi, __nv_bfloat16* __restrict__ lo,
    const float* __restrict__ src, int n4)
{
    int i = blockIdx.x * 256 + threadIdx.x;
    if (i >= n4) return;
    float4 v = ((const float4*)src)[i];
    __nv_bfloat16 h[4], l[4];
    fsplit_bf16(v.x, h[0], l[0]);
    fsplit_bf16(v.y, h[1], l[1]);
    fsplit_bf16(v.z, h[2], l[2]);
    fsplit_bf16(v.w, h[3], l[3]);
    ((uint2*)hi)[i] = *(uint2*)h;
    ((uint2*)lo)[i] = *(uint2*)l;
}

// ============================================================
// bf16 3-term split GEMM via mma.sync.m16n8k16 (unchanged from R6)
// ============================================================
#define TSTRIDE 36
#define ABYTES  (128 * TSTRIDE * 4)
#define SBYTES  (4 * ABYTES)
#define GEMM_SMEM (3 * SBYTES)

__global__ void __launch_bounds__(256, 1) gemm_bf16(
    const __nv_bfloat16* __restrict__ Ah, const __nv_bfloat16* __restrict__ Al, int K,
    const __nv_bfloat16* __restrict__ Wh, const __nv_bfloat16* __restrict__ Wl,
    size_t off0, float* __restrict__ C0, int nx0, int N0,
    size_t off1, float* __restrict__ C1,
    size_t off2, float* __restrict__ C2)
{
    extern __shared__ char sm[];
    const int tid = threadIdx.x;
    const int wid = tid >> 5;
    const int lane = tid & 31;
    const int lr = lane >> 2;
    const int lc = lane & 3;
    const int wm = wid & 3;
    const int wn = wid >> 2;

    int bx = blockIdx.x;
    size_t woff;
    float* Cp;
    int N;
    if (bx < nx0)       { woff = off0; Cp = C0; N = N0; }
    else if (bx == nx0) { woff = off1; Cp = C1; N = 128; bx = 0; }
    else                { woff = off2; Cp = C2; N = 128; bx = 0; }
    const __nv_bfloat16* Bh = Wh + woff;
    const __nv_bfloat16* Bl = Wl + woff;
    const int m0 = blockIdx.y * 128;
    const int n0 = bx * 128;
    const int NC = K >> 6;

    const uint32_t smb = smem_u32(sm);
    int grow[4], gc16[4];
    uint32_t sdst[4];
#pragma unroll
    for (int j = 0; j < 4; j++) {
        int seg = tid + j * 256;
        grow[j] = seg >> 3;
        gc16[j] = seg & 7;
        sdst[j] = (uint32_t)(grow[j] * (TSTRIDE * 4) + gc16[j] * 16);
    }

    float acc[2][8][4];
#pragma unroll
    for (int mt = 0; mt < 2; mt++)
#pragma unroll
        for (int nt = 0; nt < 8; nt++)
#pragma unroll
            for (int c = 0; c < 4; c++) acc[mt][nt][c] = 0.f;

#pragma unroll
    for (int pc = 0; pc < 2; pc++) {
        const uint32_t so = smb + (uint32_t)pc * SBYTES;
        const int kt = pc << 6;
#pragma unroll
        for (int j = 0; j < 4; j++) {
            size_t ao = (size_t)(m0 + grow[j]) * K + kt + gc16[j] * 8;
            size_t bo = (size_t)(n0 + grow[j]) * K + kt + gc16[j] * 8;
            CP_ASYNC16(so + sdst[j],              Ah + ao);
            CP_ASYNC16(so + ABYTES + sdst[j],     Al + ao);
            CP_ASYNC16(so + 2 * ABYTES + sdst[j], Bh + bo);
            CP_ASYNC16(so + 3 * ABYTES + sdst[j], Bl + bo);
        }
        CP_COMMIT();
    }

    int bufi = 0;
    for (int i = 0; i < NC; i++) {
        if (i + 2 < NC) {
            int dsti = bufi + 2; if (dsti >= 3) dsti -= 3;
            const uint32_t so = smb + (uint32_t)dsti * SBYTES;
            const int kt = (i + 2) << 6;
#pragma unroll
            for (int j = 0; j < 4; j++) {
                size_t ao = (size_t)(m0 + grow[j]) * K + kt + gc16[j] * 8;
                size_t bo = (size_t)(n0 + grow[j]) * K + kt + gc16[j] * 8;
                CP_ASYNC16(so + sdst[j],              Ah + ao);
                CP_ASYNC16(so + ABYTES + sdst[j],     Al + ao);
                CP_ASYNC16(so + 2 * ABYTES + sdst[j], Bh + bo);
                CP_ASYNC16(so + 3 * ABYTES + sdst[j], Bl + bo);
            }
        }
        CP_COMMIT();
        CP_WAIT(2);
        __syncthreads();

        const uint32_t* Ahs = (const uint32_t*)(sm + (size_t)bufi * SBYTES);
        const uint32_t* Als = (const uint32_t*)(sm + (size_t)bufi * SBYTES + ABYTES);
        const uint32_t* Bhs = (const uint32_t*)(sm + (size_t)bufi * SBYTES + 2 * ABYTES);
        const uint32_t* Bls = (const uint32_t*)(sm + (size_t)bufi * SBYTES + 3 * ABYTES);

#pragma unroll
        for (int ks = 0; ks < 4; ks++) {
            const int kc = ks * 8 + lc;
            uint32_t ah[2][4], al[2][4];
#pragma unroll
            for (int mt = 0; mt < 2; mt++) {
                const int r = wm * 32 + mt * 16 + lr;
                ah[mt][0] = Ahs[r * TSTRIDE + kc];
                ah[mt][1] = Ahs[(r + 8) * TSTRIDE + kc];
                ah[mt][2] = Ahs[r * TSTRIDE + kc + 4];
                ah[mt][3] = Ahs[(r + 8) * TSTRIDE + kc + 4];
                al[mt][0] = Als[r * TSTRIDE + kc];
                al[mt][1] = Als[(r + 8) * TSTRIDE + kc];
                al[mt][2] = Als[r * TSTRIDE + kc + 4];
                al[mt][3] = Als[(r + 8) * TSTRIDE + kc + 4];
            }
            uint32_t bh[8][2], bl[8][2];
#pragma unroll
            for (int nt = 0; nt < 8; nt++) {
                const int n = wn * 64 + nt * 8 + lr;
                bh[nt][0] = Bhs[n * TSTRIDE + kc];
                bh[nt][1] = Bhs[n * TSTRIDE + kc + 4];
                bl[nt][0] = Bls[n * TSTRIDE + kc];
                bl[nt][1] = Bls[n * TSTRIDE + kc + 4];
            }
#pragma unroll
            for (int mt = 0; mt < 2; mt++)
#pragma unroll
                for (int nt = 0; nt < 8; nt++) {
                    mma_bf16(acc[mt][nt], ah[mt][0], ah[mt][1], ah[mt][2], ah[mt][3],
                             bh[nt][0], bh[nt][1]);
                    mma_bf16(acc[mt][nt], ah[mt][0], ah[mt][1], ah[mt][2], ah[mt][3],
                             bl[nt][0], bl[nt][1]);
                    mma_bf16(acc[mt][nt], al[mt][0], al[mt][1], al[mt][2], al[mt][3],
                             bh[nt][0], bh[nt][1]);
                }
        }
        __syncthreads();
        if (++bufi == 3) bufi = 0;
    }

#pragma unroll
    for (int mt = 0; mt < 2; mt++) {
        const int r = m0 + wm * 32 + mt * 16 + lr;
#pragma unroll
        for (int nt = 0; nt < 8; nt++) {
            const int cN = n0 + wn * 64 + nt * 8 + 2 * lc;
            *(float2*)(Cp + (size_t)r * N + cN) =
                make_float2(acc[mt][nt][0], acc[mt][nt][1]);
            *(float2*)(Cp + (size_t)(r + 8) * N + cN) =
                make_float2(acc[mt][nt][2], acc[mt][nt][3]);
        }
    }
}

// ============================================================
// fused RMS kernels
// ============================================================
__device__ __forceinline__ void rms_row(float* row, const float* g, int C,
                                        const float* mean, int tid)
{
    float vr[4];
    int cnt = C >> 7;
    float ss = 0.f;
#pragma unroll 4
    for (int j = 0; j < cnt; j++) {
        int i = tid + j * 128;
        float v = row[i];
        if (mean) v += GAINc * mean[i & 31];
        vr[j] = v;
        ss += v * v;
    }
#pragma unroll
    for (int o = 16; o; o >>= 1) ss += __shfl_xor_sync(~0u, ss, o);
    __shared__ float ws[4];
    if ((tid & 31) == 0) ws[tid >> 5] = ss;
    __syncthreads();
    float tot = ws[0] + ws[1] + ws[2] + ws[3];
    float r = rsqrtf(tot / (float)C + EPSc);
#pragma unroll 4
    for (int j = 0; j < cnt; j++) {
        int i = tid + j * 128;
        row[i] = vr[j] * r * g[i];
    }
}

__global__ void __launch_bounds__(128) rms3(
    float* pa, const float* ga, int Ca,
    float* pb, const float* gb, int Cb,
    float* pc, const float* gc, int Cc)
{
    int t = blockIdx.x;
    if (t < Tc)          rms_row(pa + (size_t)t * Ca, ga, Ca, nullptr, threadIdx.x);
    else if (t < 2 * Tc) rms_row(pb + (size_t)(t - Tc) * Cb, gb, Cb, nullptr, threadIdx.x);
    else                 rms_row(pc + (size_t)(t - 2 * Tc) * Cc, gc, Cc, nullptr, threadIdx.x);
}

__global__ void __launch_bounds__(128) rms2(
    float* pa, const float* ga, int Ca, const float* ma,
    float* pb, const float* gb, int Cb, const float* mb)
{
    int t = blockIdx.x;
    if (t < Tc) rms_row(pa + (size_t)t * Ca, ga, Ca, ma ? ma + (size_t)t * 32 : nullptr, threadIdx.x);
    else {
        t -= Tc;
        rms_row(pb + (size_t)t * Cb, gb, Cb, mb ? mb + (size_t)t * 32 : nullptr, threadIdx.x);
    }
}

__global__ void __launch_bounds__(128) rms_split(
    const float* __restrict__ x, const float* __restrict__ g,
    __nv_bfloat16* __restrict__ hi, __nv_bfloat16* __restrict__ lo)
{
    const int t = blockIdx.x;
    const float* row = x + (size_t)t * LATc;
    const int tid = threadIdx.x;
    float vr[4];
    float ss = 0.f;
#pragma unroll
    for (int j = 0; j < 4; j++) {
        float v = row[tid + j * 128];
        vr[j] = v;
        ss += v * v;
    }
#pragma unroll
    for (int o = 16; o; o >>= 1) ss += __shfl_xor_sync(~0u, ss, o);
    __shared__ float ws[4];
    if ((tid & 31) == 0) ws[tid >> 5] = ss;
    __syncthreads();
    float tot = ws[0] + ws[1] + ws[2] + ws[3];
    float r = rsqrtf(tot / (float)LATc + EPSc);
#pragma unroll
    for (int j = 0; j < 4; j++) {
        int i = tid + j * 128;
        float y = vr[j] * r * g[i];
        __nv_bfloat16 h, l;
        fsplit_bf16(y, h, l);
        hi[(size_t)t * LATc + i] = h;
        lo[(size_t)t * LATc + i] = l;
    }
}

// ============================================================
// Grouped causal conv (tiled), K=3, 32 ch/group
// ============================================================
__global__ void __launch_bounds__(256) conv_causal_t(
    float* __restrict__ y, const float* __restrict__ x,
    const float* __restrict__ w, int C)
{
    __shared__ float ws[96][33];
    __shared__ float xs[66][32];
    const int tid = threadIdx.x;
    const int t0 = blockIdx.x * 64;
    const int base = blockIdx.y * 32;
    const int s0 = t0 & (Sc - 1);

    for (int idx = tid; idx < 3072; idx += 256) {
        int co = idx / 96;
        int r = idx - co * 96;
        ws[r][co] = w[(size_t)(base + co) * 96 + r];
    }
    for (int idx = tid; idx < 66 * 32; idx += 256) {
        int row = idx >> 5;
        int ci = idx & 31;
        int srow = s0 - 2 + row;
        xs[row][ci] = (srow >= 0 && row < 66)
            ? x[(size_t)(t0 - 2 + row) * C + base + ci] : 0.f;
    }
    __syncthreads();

    const int co = tid & 31;
    const int tg = tid >> 5;
#pragma unroll
    for (int tk = 0; tk < 8; tk++) {
        const int tt = tg * 8 + tk;
        float acc = 0.f;
#pragma unroll 8
        for (int ci = 0; ci < 32; ci++) {
#pragma unroll
            for (int j = 0; j < 3; j++)
                acc += ws[ci * 3 + j][co] * xs[tt + j][ci];
        }
        y[(size_t)(t0 + tt) * C + base + co] = acc;
    }
}

// ============================================================
// Per-token head-mean
// ============================================================
__global__ void __launch_bounds__(256) head_mean(
    float* __restrict__ out, const float* __restrict__ x, int C, int heads)
{
    const int idx = blockIdx.x * 256 + threadIdx.x;
    if (idx >= Tc * HDc) return;
    const int t = idx >> 5;
    const int d = idx & 31;
    const float* row = x + (size_t)t * C + d;
    float s = 0.f;
    for (int h = 0; h < heads; h++) s += row[h * 32];
    out[idx] = s / (float)heads;
}

// ============================================================
// merged q+k per-head L2 norm + RoPE -> bf16 hi/lo splits
// ============================================================
__global__ void __launch_bounds__(128) headnorm_rope2(
    const float* __restrict__ xq, const float* __restrict__ xk,
    __nv_bfloat16* __restrict__ qsh, __nv_bfloat16* __restrict__ qsl,
    __nv_bfloat16* __restrict__ ksh, __nv_bfloat16* __restrict__ ksl,
    const float* __restrict__ key_temp)
{
    const int idx = blockIdx.x * 128 + threadIdx.x;
    const float* p;
    __nv_bfloat16 *oh, *ol;
    size_t off;
    int s, is_k;
    if (idx < Tc * NHc) {
        int t = idx >> 4;
        int h = idx & 15;
        off = (size_t)t * LATc + h * 32;
        p = xq + off; oh = qsh; ol = qsl;
        s = t & (Sc - 1);
        is_k = 0;
    } else {
        int j = idx - Tc * NHc;
        int t = j >> 2;
        int h = j & 3;
        off = (size_t)t * KVDc + h * 32;
        p = xk + off; oh = ksh; ol = ksl;
        s = t & (Sc - 1);
        is_k = 1;
    }
    float v[32];
    float ss = 0.f;
#pragma unroll
    for (int d = 0; d < 32; d++) { v[d] = p[d]; ss += v[d] * v[d]; }
    float n = fmaxf(sqrtf(ss), 1e-12f);
    float f = is_k ? (5.656854249492380f * key_temp[0] / n) : (1.0f / n);
#pragma unroll
    for (int d = 0; d < 32; d++) v[d] *= f;
#pragma unroll
    for (int i = 0; i < 16; i++) {
        float fr = expf(-(float)i * 0.575646273248511f);
        float ang = (float)s * fr;
        float sn, cs;
        sincosf(ang, &sn, &cs);
        float x1 = v[2 * i], x2 = v[2 * i + 1];
        v[2 * i]     = x1 * cs - x2 * sn;
        v[2 * i + 1] = x1 * sn + x2 * cs;
    }
    uint32_t* oh32 = (uint32_t*)(oh + off);
    uint32_t* ol32 = (uint32_t*)(ol + off);
#pragma unroll
    for (int d = 0; d < 16; d++) {
        uint32_t hi, lo;
        pack_split2(v[2 * d], v[2 * d + 1], hi, lo);
        oh32[d] = hi;
        ol32[d] = lo;
    }
}

// ============================================================
// V transpose + bf16 split: [b,key,kvh,dim] fp32 -> [b,kvh,dim,key] bf16 x2
// ============================================================
__global__ void __launch_bounds__(256) vtrans(
    const float* __restrict__ v,
    __nv_bfloat16* __restrict__ vh, __nv_bfloat16* __restrict__ vl)
{
    __shared__ float ts[32][33];
    const int j0 = blockIdx.x * 32;
    const int bk = blockIdx.y;          // b*4 + kvh
    const int b = bk >> 2, kv = bk & 3;
    const int tid = threadIdx.x;
    {
        int ky = tid >> 3, d4 = (tid & 7) * 4;
        float4 val = *(const float4*)(v + (size_t)(b * Sc + j0 + ky) * KVDc + kv * 32 + d4);
        ts[ky][d4 + 0] = val.x; ts[ky][d4 + 1] = val.y;
        ts[ky][d4 + 2] = val.z; ts[ky][d4 + 3] = val.w;
    }
    __syncthreads();
    int d = tid >> 3, kp = (tid & 7) * 4;
    __nv_bfloat16 hb[4], lb[4];
#pragma unroll
    for (int i = 0; i < 4; i++)
        fsplit_bf16(ts[kp + i][d], hb[i], lb[i]);
    size_t dst = ((size_t)bk * 32 + d) * Sc + j0 + kp;
    *(uint2*)(vh + dst) = *(uint2*)hb;
    *(uint2*)(vl + dst) = *(uint2*)lb;
}

// ============================================================
// mma flash attention: block = 128 q rows x (b,h); 64-key tiles,
// double-buffered cp.async; softmax via FFMA exp2 poly.
// ============================================================
__global__ void __launch_bounds__(256) flash_mma(
    float* __restrict__ o,
    const __nv_bfloat16* __restrict__ qh, const __nv_bfloat16* __restrict__ ql,
    const __nv_bfloat16* __restrict__ kh, const __nv_bfloat16* __restrict__ kl,
    const __nv_bfloat16* __restrict__ vth, const __nv_bfloat16* __restrict__ vtl)
{
    __shared__ uint32_t sK[2][2][64 * 20];
    __shared__ uint32_t sV[2][2][32 * 36];
    const int bh = blockIdx.y;
    const int b  = bh >> 4;
    const int h  = bh & 15;
    const int kv = h >> 2;
    const int sq0 = blockIdx.x * 128;
    const int tid = threadIdx.x;
    const int wq  = tid >> 5;
    const int lane = tid & 31;
    const int lr = lane >> 2;
    const int lc = lane & 3;

    // Q fragments (2 k-steps x 4 regs, hi & lo)
    uint32_t qfh[2][4], qfl[2][4];
    {
        const int r0 = b * Sc + sq0 + wq * 16 + lr;
        const uint32_t* q0h = (const uint32_t*)(qh + (size_t)r0 * LATc + h * 32);
        const uint32_t* q8h = (const uint32_t*)(qh + (size_t)(r0 + 8) * LATc + h * 32);
        const uint32_t* q0l = (const uint32_t*)(ql + (size_t)r0 * LATc + h * 32);
        const uint32_t* q8l = (const uint32_t*)(ql + (size_t)(r0 + 8) * LATc + h * 32);
#pragma unroll
        for (int s = 0; s < 2; s++) {
            qfh[s][0] = q0h[8 * s + lc];
            qfh[s][1] = q8h[8 * s + lc];
            qfh[s][2] = q0h[8 * s + lc + 4];
            qfh[s][3] = q8h[8 * s + lc + 4];
            qfl[s][0] = q0l[8 * s + lc];
            qfl[s][1] = q8l[8 * s + lc];
            qfl[s][2] = q0l[8 * s + lc + 4];
            qfl[s][3] = q8l[8 * s + lc + 4];
        }
    }
    float oacc[4][4];
#pragma unroll
    for (int vn = 0; vn < 4; vn++)
#pragma unroll
        for (int c = 0; c < 4; c++) oacc[vn][c] = 0.f;
    float m0 = -1e30f, m1 = -1e30f, l0 = 0.f, l1 = 0.f;
    const int ntile = (sq0 >> 6) + 2;

#define LOAD_TILE(st, j0v) do { \
    const size_t gk = (size_t)(b * Sc + (j0v)); \
    for (int u = tid; u < 512; u += 256) { \
        int row = u >> 3, pp = u & 7; \
        CP_ASYNC8(smem_u32(&sK[st][0][row * 20 + pp * 2]), \
                  kh + (gk + row) * KVDc + kv * 32 + pp * 4); \
        CP_ASYNC8(smem_u32(&sK[st][1][row * 20 + pp * 2]), \
                  kl + (gk + row) * KVDc + kv * 32 + pp * 4); \
    } \
    { \
        int d = tid >> 3, q8 = tid & 7; \
        const size_t vs = ((size_t)(b * 4 + kv) * 32 + d) * Sc + (j0v) + q8 * 8; \
        CP_ASYNC16(smem_u32(&sV[st][0][d * 36 + q8 * 4]), vth + vs); \
        CP_ASYNC16(smem_u32(&sV[st][1][d * 36 + q8 * 4]), vtl + vs); \
    } \
} while (0)

    LOAD_TILE(0, 0);
    CP_COMMIT();

    for (int jt = 0; jt < ntile; jt++) {
        const int st = jt & 1;
        const int j0 = jt << 6;
        if (jt + 1 < ntile) {
            LOAD_TILE(st ^ 1, j0 + 64);
            CP_COMMIT();
            CP_WAIT(1);
        } else {
            CP_WAIT(0);
        }
        __syncthreads();

        // ---- QK^T ----
        float sacc[8][4];
#pragma unroll
        for (int nt = 0; nt < 8; nt++)
#pragma unroll
            for (int c = 0; c < 4; c++) sacc[nt][c] = 0.f;
#pragma unroll
        for (int s = 0; s < 2; s++) {
#pragma unroll
            for (int nt = 0; nt < 8; nt++) {
                const uint32_t* Kr0 = &sK[st][0][(nt * 8 + lr) * 20 + 8 * s + lc];
                const uint32_t* Kr1 = &sK[st][1][(nt * 8 + lr) * 20 + 8 * s + lc];
                uint32_t b0 = Kr0[0], b1 = Kr0[4];
                uint32_t c0 = Kr1[0], c1 = Kr1[4];
                mma_bf16(sacc[nt], qfh[s][0], qfh[s][1], qfh[s][2], qfh[s][3], b0, b1);
                mma_bf16(sacc[nt], qfh[s][0], qfh[s][1], qfh[s][2], qfh[s][3], c0, c1);
                mma_bf16(sacc[nt], qfl[s][0], qfl[s][1], qfl[s][2], qfl[s][3], b0, b1);
            }
        }
        // ---- causal mask ----
        const int r0 = sq0 + wq * 16 + lr;
        const int r1 = r0 + 8;
        const bool full = (j0 + 63) <= (sq0 + wq * 16);
        if (!full) {
#pragma unroll
            for (int nt = 0; nt < 8; nt++) {
                int kb = j0 + nt * 8 + 2 * lc;
                if (kb     > r0) sacc[nt][0] = -1e30f;
                if (kb + 1 > r0) sacc[nt][1] = -1e30f;
                if (kb     > r1) sacc[nt][2] = -1e30f;
                if (kb + 1 > r1) sacc[nt][3] = -1e30f;
            }
        }
        // ---- row max ----
        float mx0 = -1e30f, mx1 = -1e30f;
#pragma unroll
        for (int nt = 0; nt < 8; nt++) {
            mx0 = fmaxf(mx0, fmaxf(sacc[nt][0], sacc[nt][1]));
            mx1 = fmaxf(mx1, fmaxf(sacc[nt][2], sacc[nt][3]));
        }
        mx0 = fmaxf(mx0, __shfl_xor_sync(~0u, mx0, 1));
        mx0 = fmaxf(mx0, __shfl_xor_sync(~0u, mx0, 2));
        mx1 = fmaxf(mx1, __shfl_xor_sync(~0u, mx1, 1));
        mx1 = fmaxf(mx1, __shfl_xor_sync(~0u, mx1, 2));
        float nm0 = fmaxf(m0, mx0);
        float nm1 = fmaxf(m1, mx1);
        float a0e = fexp2((m0 - nm0) * L2E);
        float a1e = fexp2((m1 - nm1) * L2E);
        m0 = nm0; m1 = nm1;
        l0 *= a0e; l1 *= a1e;
#pragma unroll
        for (int vn = 0; vn < 4; vn++) {
            oacc[vn][0] *= a0e; oacc[vn][1] *= a0e;
            oacc[vn][2] *= a1e; oacc[vn][3] *= a1e;
        }
        // ---- P = exp, pack, PV ----
#pragma unroll
        for (int s2 = 0; s2 < 4; s2++) {
            float p0a = fexp2((sacc[2 * s2][0] - nm0) * L2E);
            float p0b = fexp2((sacc[2 * s2][1] - nm0) * L2E);
            float p8a = fexp2((sacc[2 * s2][2] - nm1) * L2E);
            float p8b = fexp2((sacc[2 * s2][3] - nm1) * L2E);
            float q0a = fexp2((sacc[2 * s2 + 1][0] - nm0) * L2E);
            float q0b = fexp2((sacc[2 * s2 + 1][1] - nm0) * L2E);
            float q8a = fexp2((sacc[2 * s2 + 1][2] - nm1) * L2E);
            float q8b = fexp2((sacc[2 * s2 + 1][3] - nm1) * L2E);
            l0 += p0a + p0b + q0a + q0b;
            l1 += p8a + p8b + q8a + q8b;
            uint32_t pha[4], pla[4];
            pack_split2(p0a, p0b, pha[0], pla[0]);
            pack_split2(p8a, p8b, pha[1], pla[1]);
            pack_split2(q0a, q0b, pha[2], pla[2]);
            pack_split2(q8a, q8b, pha[3], pla[3]);
#pragma unroll
            for (int vn = 0; vn < 4; vn++) {
                const uint32_t* Vr0 = &sV[st][0][(vn * 8 + lr) * 36 + 8 * s2 + lc];
                const uint32_t* Vr1 = &sV[st][1][(vn * 8 + lr) * 36 + 8 * s2 + lc];
                uint32_t b0 = Vr0[0], b1 = Vr0[4];
                uint32_t c0 = Vr1[0], c1 = Vr1[4];
                mma_bf16(oacc[vn], pha[0], pha[1], pha[2], pha[3], b0, b1);
                mma_bf16(oacc[vn], pha[0], pha[1], pha[2], pha[3], c0, c1);
                mma_bf16(oacc[vn], pla[0], pla[1], pla[2], pla[3], b0, b1);
            }
        }
        __syncthreads();
    }

    l0 += __shfl_xor_sync(~0u, l0, 1);
    l0 += __shfl_xor_sync(~0u, l0, 2);
    l1 += __shfl_xor_sync(~0u, l1, 1);
    l1 += __shfl_xor_sync(~0u, l1, 2);
    float i0 = 1.f / l0, i1 = 1.f / l1;
    const int gr0 = b * Sc + sq0 + wq * 16 + lr;
    float* o0 = o + (size_t)gr0 * LATc + h * 32;
    float* o8 = o + (size_t)(gr0 + 8) * LATc + h * 32;
#pragma unroll
    for (int vn = 0; vn < 4; vn++) {
        *(float2*)(o0 + vn * 8 + 2 * lc) = make_float2(oacc[vn][0] * i0, oacc[vn][1] * i0);
        *(float2*)(o8 + vn * 8 + 2 * lc) = make_float2(oacc[vn][2] * i1, oacc[vn][3] * i1);
    }
}

// ============================================================
// host launcher
// ============================================================
extern "C" void kernel_launch(void* const* d_in, const int* in_sizes, int n_in,
                              void* d_out, int out_size)
{
    const float* x        = (const float*)d_in[0];
    const float* w_q      = (const float*)d_in[1];
    const float* w_k      = (const float*)d_in[2];
    const float* w_v      = (const float*)d_in[3];
    const float* g_latent = (const float*)d_in[4];
    const float* g_kv     = (const float*)d_in[5];
    const float* conv_q_w = (const float*)d_in[6];
    const float* conv_k_w = (const float*)d_in[7];
    const float* g_conv   = (const float*)d_in[8];
    const float* g_kconv  = (const float*)d_in[9];
    const float* g_postq  = (const float*)d_in[10];
    const float* g_postk  = (const float*)d_in[11];
    const float* key_temp = (const float*)d_in[12];
    const float* g_preout = (const float*)d_in[13];
    const float* w_o      = (const float*)d_in[14];
    float* out = (float*)d_out;

    float *pq, *pk, *pv, *pqc, *pkc, *pqm, *pkm, *po;
    __nv_bfloat16 *pxh, *pxl, *pwh, *pwl, *pph, *ppl;
    __nv_bfloat16 *pqh, *pql2, *pkh, *pkl, *pvth, *pvtl;
    cudaGetSymbolAddress((void**)&pq,  g_q);
    cudaGetSymbolAddress((void**)&pk,  g_k);
    cudaGetSymbolAddress((void**)&pv,  g_v);
    cudaGetSymbolAddress((void**)&pqc, g_qc);
    cudaGetSymbolAddress((void**)&pkc, g_kc);
    cudaGetSymbolAddress((void**)&pqm, g_qm);
    cudaGetSymbolAddress((void**)&pkm, g_km);
    cudaGetSymbolAddress((void**)&po,  g_o);
    cudaGetSymbolAddress((void**)&pxh, gb_xh);
    cudaGetSymbolAddress((void**)&pxl, gb_xl);
    cudaGetSymbolAddress((void**)&pwh, gb_wh);
    cudaGetSymbolAddress((void**)&pwl, gb_wl);
    cudaGetSymbolAddress((void**)&pph, gb_ph);
    cudaGetSymbolAddress((void**)&ppl, gb_pl);
    cudaGetSymbolAddress((void**)&pqh, gb_qh);
    cudaGetSymbolAddress((void**)&pql2, gb_ql);
    cudaGetSymbolAddress((void**)&pkh, gb_kh);
    cudaGetSymbolAddress((void**)&pkl, gb_kl);
    cudaGetSymbolAddress((void**)&pvth, gb_vth);
    cudaGetSymbolAddress((void**)&pvtl, gb_vtl);

    cudaFuncSetAttribute(gemm_bf16, cudaFuncAttributeMaxDynamicSharedMemorySize, GEMM_SMEM);

    // 0) pre-split x and weights into bf16 hi/lo
    split_arr<<<(Tc * Dc / 4 + 255) / 256, 256>>>(pxh, pxl, x, Tc * Dc / 4);
    split_arr<<<(LATc * Dc / 4 + 255) / 256, 256>>>(pwh + OFF_WQ, pwl + OFF_WQ, w_q, LATc * Dc / 4);
    split_arr<<<(KVDc * Dc / 4 + 255) / 256, 256>>>(pwh + OFF_WK, pwl + OFF_WK, w_k, KVDc * Dc / 4);
    split_arr<<<(KVDc * Dc / 4 + 255) / 256, 256>>>(pwh + OFF_WV, pwl + OFF_WV, w_v, KVDc * Dc / 4);
    split_arr<<<(Dc * LATc / 4 + 255) / 256, 256>>>(pwh + OFF_WO, pwl + OFF_WO, w_o, Dc * LATc / 4);

    // 1) fused q/k/v projections
    gemm_bf16<<<dim3(6, Tc / 128), 256, GEMM_SMEM>>>(
        pxh, pxl, Dc, pwh, pwl,
        OFF_WQ, pq, 4, LATc, OFF_WK, pk, OFF_WV, pv);

    // 2) first RMS norms
    rms3<<<3 * Tc, 128>>>(pq, g_latent, LATc, pk, g_kv, KVDc, pv, g_kv, KVDc);

    // 3) causal grouped conv + RMS
    conv_causal_t<<<dim3(Tc / 64, LATc / 32), 256>>>(pqc, pq, conv_q_w, LATc);
    conv_causal_t<<<dim3(Tc / 64, KVDc / 32), 256>>>(pkc, pk, conv_k_w, KVDc);
    rms2<<<2 * Tc, 128>>>(pqc, g_conv, LATc, nullptr, pkc, g_kconv, KVDc, nullptr);

    // 4) cross-coupling means + post RMS (mean-add fused)
    head_mean<<<(Tc * HDc) / 256, 256>>>(pqm, pq, LATc, NHc);
    head_mean<<<(Tc * HDc) / 256, 256>>>(pkm, pk, KVDc, NKVc);
    rms2<<<2 * Tc, 128>>>(pqc, g_postq, LATc, pkm, pkc, g_postk, KVDc, pqm);

    // 5) per-head L2 norm + RoPE -> bf16 splits; V transpose+split
    headnorm_rope2<<<(Tc * (NHc + NKVc)) / 128, 128>>>(
        pqc, pkc, pqh, pql2, pkh, pkl, key_temp);
    vtrans<<<dim3(Sc / 32, Bc * NKVc), 256>>>(pv, pvth, pvtl);

    // 6) mma causal attention
    flash_mma<<<dim3(Sc / 128, Bc * NHc), 256>>>(po, pqh, pql2, pkh, pkl, pvth, pvtl);

    // 7) pre-out RMS fused with bf16 split, then output projection
    rms_split<<<Tc, 128>>>(po, g_preout, pph, ppl);
    gemm_bf16<<<dim3(16, Tc / 128), 256, GEMM_SMEM>>>(
        pph, ppl, LATc, pwh, pwl,
        OFF_WO, out, 16, Dc, 0, nullptr, 0, nullptr);
}

// round 9
// speedup vs baseline: 1.9598x; 1.0279x over previous
#include <cuda_runtime.h>
#include <cuda_bf16.h>
#include <math.h>
#include <cstdint>

#define Bc   4
#define Sc   2048
#define Dc   2048
#define LATc 512
#define NHc  16
#define NKVc 4
#define HDc  32
#define KVDc 128
#define Tc   (Bc * Sc)
#define GAINc 0.25f
#define EPSc  1e-6f
#define L2E  1.4426950408889634f

#define OFF_WQ 0
#define OFF_WK (LATc * Dc)
#define OFF_WV (OFF_WK + KVDc * Dc)
#define OFF_WO (OFF_WV + KVDc * Dc)
#define WTOT   (OFF_WO + Dc * LATc)

// -------- scratch --------
__device__ float g_q [Tc * LATc];
__device__ float g_k [Tc * KVDc];
__device__ float g_v [Tc * KVDc];
__device__ float g_qc[Tc * LATc];
__device__ float g_kc[Tc * KVDc];
__device__ float g_o [Tc * LATc];
__device__ float2 g_rope[Sc * 16];
__device__ __nv_bfloat16 gb_xh[Tc * Dc];
__device__ __nv_bfloat16 gb_xl[Tc * Dc];
__device__ __nv_bfloat16 gb_wh[WTOT];
__device__ __nv_bfloat16 gb_wl[WTOT];
__device__ __nv_bfloat16 gb_ph[Tc * LATc];
__device__ __nv_bfloat16 gb_pl[Tc * LATc];
__device__ __nv_bfloat16 gb_qh[Tc * LATc];
__device__ __nv_bfloat16 gb_ql[Tc * LATc];
__device__ __nv_bfloat16 gb_kh[Tc * KVDc];
__device__ __nv_bfloat16 gb_kl[Tc * KVDc];
__device__ __nv_bfloat16 gb_vth[Tc * KVDc];
__device__ __nv_bfloat16 gb_vtl[Tc * KVDc];

// ---------------- helpers ----------------
__device__ __forceinline__ void mma_bf16(float* d, uint32_t a0, uint32_t a1,
                                         uint32_t a2, uint32_t a3,
                                         uint32_t b0, uint32_t b1) {
    asm volatile(
        "mma.sync.aligned.m16n8k16.row.col.f32.bf16.bf16.f32 "
        "{%0,%1,%2,%3}, {%4,%5,%6,%7}, {%8,%9}, {%0,%1,%2,%3};"
        : "+f"(d[0]), "+f"(d[1]), "+f"(d[2]), "+f"(d[3])
        : "r"(a0), "r"(a1), "r"(a2), "r"(a3), "r"(b0), "r"(b1));
}
__device__ __forceinline__ void fsplit_bf16(float x, __nv_bfloat16& h, __nv_bfloat16& l) {
    h = __float2bfloat16_rn(x);
    l = __float2bfloat16_rn(x - __bfloat162float(h));
}
__device__ __forceinline__ uint32_t smem_u32(const void* p) {
    uint32_t a;
    asm("{ .reg .u64 t; cvta.to.shared.u64 t, %1; cvt.u32.u64 %0, t; }" : "=r"(a) : "l"(p));
    return a;
}
#define CP_ASYNC16(dst, src) \
    asm volatile("cp.async.cg.shared.global [%0], [%1], 16;" :: "r"(dst), "l"(src))
#define CP_ASYNC8(dst, src) \
    asm volatile("cp.async.ca.shared.global [%0], [%1], 8;" :: "r"(dst), "l"(src))
#define CP_COMMIT() asm volatile("cp.async.commit_group;" ::: "memory")
#define CP_WAIT(n)  asm volatile("cp.async.wait_group %0;" :: "n"(n) : "memory")

__device__ __forceinline__ float fexp2(float t) {
    t = fmaxf(t, -126.f);
    float fi = floorf(t);
    float f = t - fi;
    int i = (int)fi;
    float p = 1.5403530393381609e-4f;
    p = fmaf(p, f, 1.3333558146428443e-3f);
    p = fmaf(p, f, 9.6181291076284772e-3f);
    p = fmaf(p, f, 5.5504108664821580e-2f);
    p = fmaf(p, f, 2.4022650695910072e-1f);
    p = fmaf(p, f, 6.9314718055994531e-1f);
    p = fmaf(p, f, 1.0f);
    return p * __int_as_float((i + 127) << 23);
}
__device__ __forceinline__ void pack_split2(float a, float b, uint32_t& hi, uint32_t& lo) {
    __nv_bfloat16 ha = __float2bfloat16_rn(a);
    __nv_bfloat16 hb = __float2bfloat16_rn(b);
    __nv_bfloat16 la = __float2bfloat16_rn(a - __bfloat162float(ha));
    __nv_bfloat16 lb = __float2bfloat16_rn(b - __bfloat162float(hb));
    __nv_bfloat162 H; H.x = ha; H.y = hb;
    __nv_bfloat162 L; L.x = la; L.y = lb;
    hi = *(uint32_t*)&H; lo = *(uint32_t*)&L;
}

// ============================================================
// rope tables: g_rope[s*16+i] = (cos, sin)(s * theta^(-i/16))
// ============================================================
__global__ void __launch_bounds__(256) rope_tab(float2* __restrict__ rt)
{
    int idx = blockIdx.x * 256 + threadIdx.x;
    if (idx >= Sc * 16) return;
    int s = idx >> 4, i = idx & 15;
    float fr = expf(-(float)i * 0.575646273248511f);
    float sn, cs;
    sincosf((float)s * fr, &sn, &cs);
    rt[idx] = make_float2(cs, sn);
}

// ============================================================
// split float array into bf16 hi/lo
// ============================================================
__global__ void __launch_bounds__(256) split_arr(
    __nv_bfloat16* __restrict__ hi, __nv_bfloat16* __restrict__ lo,
    const float* __restrict__ src, int n4)
{
    int i = blockIdx.x * 256 + threadIdx.x;
    if (i >= n4) return;
    float4 v = ((const float4*)src)[i];
    __nv_bfloat16 h[4], l[4];
    fsplit_bf16(v.x, h[0], l[0]);
    fsplit_bf16(v.y, h[1], l[1]);
    fsplit_bf16(v.z, h[2], l[2]);
    fsplit_bf16(v.w, h[3], l[3]);
    ((uint2*)hi)[i] = *(uint2*)h;
    ((uint2*)lo)[i] = *(uint2*)l;
}

// all 4 weights in one launch
__global__ void __launch_bounds__(256) split_w4(
    __nv_bfloat16* __restrict__ hi, __nv_bfloat16* __restrict__ lo,
    const float* __restrict__ wq, const float* __restrict__ wk,
    const float* __restrict__ wv, const float* __restrict__ wo)
{
    int i = blockIdx.x * 256 + threadIdx.x;   // float4 index into packed layout
    const float* src;
    int base;
    if (i < OFF_WK / 4)              { src = wq; base = 0; }
    else if (i < OFF_WV / 4)         { src = wk; base = OFF_WK / 4; }
    else if (i < OFF_WO / 4)         { src = wv; base = OFF_WV / 4; }
    else if (i < WTOT / 4)           { src = wo; base = OFF_WO / 4; }
    else return;
    float4 v = ((const float4*)src)[i - base];
    __nv_bfloat16 h[4], l[4];
    fsplit_bf16(v.x, h[0], l[0]);
    fsplit_bf16(v.y, h[1], l[1]);
    fsplit_bf16(v.z, h[2], l[2]);
    fsplit_bf16(v.w, h[3], l[3]);
    ((uint2*)hi)[i] = *(uint2*)h;
    ((uint2*)lo)[i] = *(uint2*)l;
}

// ============================================================
// bf16 3-term split GEMM (unchanged)
// ============================================================
#define TSTRIDE 36
#define ABYTES  (128 * TSTRIDE * 4)
#define SBYTES  (4 * ABYTES)
#define GEMM_SMEM (3 * SBYTES)

__global__ void __launch_bounds__(256, 1) gemm_bf16(
    const __nv_bfloat16* __restrict__ Ah, const __nv_bfloat16* __restrict__ Al, int K,
    const __nv_bfloat16* __restrict__ Wh, const __nv_bfloat16* __restrict__ Wl,
    size_t off0, float* __restrict__ C0, int nx0, int N0,
    size_t off1, float* __restrict__ C1,
    size_t off2, float* __restrict__ C2)
{
    extern __shared__ char sm[];
    const int tid = threadIdx.x;
    const int wid = tid >> 5;
    const int lane = tid & 31;
    const int lr = lane >> 2;
    const int lc = lane & 3;
    const int wm = wid & 3;
    const int wn = wid >> 2;

    int bx = blockIdx.x;
    size_t woff;
    float* Cp;
    int N;
    if (bx < nx0)       { woff = off0; Cp = C0; N = N0; }
    else if (bx == nx0) { woff = off1; Cp = C1; N = 128; bx = 0; }
    else                { woff = off2; Cp = C2; N = 128; bx = 0; }
    const __nv_bfloat16* Bh = Wh + woff;
    const __nv_bfloat16* Bl = Wl + woff;
    const int m0 = blockIdx.y * 128;
    const int n0 = bx * 128;
    const int NC = K >> 6;

    const uint32_t smb = smem_u32(sm);
    int grow[4], gc16[4];
    uint32_t sdst[4];
#pragma unroll
    for (int j = 0; j < 4; j++) {
        int seg = tid + j * 256;
        grow[j] = seg >> 3;
        gc16[j] = seg & 7;
        sdst[j] = (uint32_t)(grow[j] * (TSTRIDE * 4) + gc16[j] * 16);
    }

    float acc[2][8][4];
#pragma unroll
    for (int mt = 0; mt < 2; mt++)
#pragma unroll
        for (int nt = 0; nt < 8; nt++)
#pragma unroll
            for (int c = 0; c < 4; c++) acc[mt][nt][c] = 0.f;

#pragma unroll
    for (int pc = 0; pc < 2; pc++) {
        const uint32_t so = smb + (uint32_t)pc * SBYTES;
        const int kt = pc << 6;
#pragma unroll
        for (int j = 0; j < 4; j++) {
            size_t ao = (size_t)(m0 + grow[j]) * K + kt + gc16[j] * 8;
            size_t bo = (size_t)(n0 + grow[j]) * K + kt + gc16[j] * 8;
            CP_ASYNC16(so + sdst[j],              Ah + ao);
            CP_ASYNC16(so + ABYTES + sdst[j],     Al + ao);
            CP_ASYNC16(so + 2 * ABYTES + sdst[j], Bh + bo);
            CP_ASYNC16(so + 3 * ABYTES + sdst[j], Bl + bo);
        }
        CP_COMMIT();
    }

    int bufi = 0;
    for (int i = 0; i < NC; i++) {
        if (i + 2 < NC) {
            int dsti = bufi + 2; if (dsti >= 3) dsti -= 3;
            const uint32_t so = smb + (uint32_t)dsti * SBYTES;
            const int kt = (i + 2) << 6;
#pragma unroll
            for (int j = 0; j < 4; j++) {
                size_t ao = (size_t)(m0 + grow[j]) * K + kt + gc16[j] * 8;
                size_t bo = (size_t)(n0 + grow[j]) * K + kt + gc16[j] * 8;
                CP_ASYNC16(so + sdst[j],              Ah + ao);
                CP_ASYNC16(so + ABYTES + sdst[j],     Al + ao);
                CP_ASYNC16(so + 2 * ABYTES + sdst[j], Bh + bo);
                CP_ASYNC16(so + 3 * ABYTES + sdst[j], Bl + bo);
            }
        }
        CP_COMMIT();
        CP_WAIT(2);
        __syncthreads();

        const uint32_t* Ahs = (const uint32_t*)(sm + (size_t)bufi * SBYTES);
        const uint32_t* Als = (const uint32_t*)(sm + (size_t)bufi * SBYTES + ABYTES);
        const uint32_t* Bhs = (const uint32_t*)(sm + (size_t)bufi * SBYTES + 2 * ABYTES);
        const uint32_t* Bls = (const uint32_t*)(sm + (size_t)bufi * SBYTES + 3 * ABYTES);

#pragma unroll
        for (int ks = 0; ks < 4; ks++) {
            const int kc = ks * 8 + lc;
            uint32_t ah[2][4], al[2][4];
#pragma unroll
            for (int mt = 0; mt < 2; mt++) {
                const int r = wm * 32 + mt * 16 + lr;
                ah[mt][0] = Ahs[r * TSTRIDE + kc];
                ah[mt][1] = Ahs[(r + 8) * TSTRIDE + kc];
                ah[mt][2] = Ahs[r * TSTRIDE + kc + 4];
                ah[mt][3] = Ahs[(r + 8) * TSTRIDE + kc + 4];
                al[mt][0] = Als[r * TSTRIDE + kc];
                al[mt][1] = Als[(r + 8) * TSTRIDE + kc];
                al[mt][2] = Als[r * TSTRIDE + kc + 4];
                al[mt][3] = Als[(r + 8) * TSTRIDE + kc + 4];
            }
            uint32_t bh[8][2], bl[8][2];
#pragma unroll
            for (int nt = 0; nt < 8; nt++) {
                const int n = wn * 64 + nt * 8 + lr;
                bh[nt][0] = Bhs[n * TSTRIDE + kc];
                bh[nt][1] = Bhs[n * TSTRIDE + kc + 4];
                bl[nt][0] = Bls[n * TSTRIDE + kc];
                bl[nt][1] = Bls[n * TSTRIDE + kc + 4];
            }
#pragma unroll
            for (int mt = 0; mt < 2; mt++)
#pragma unroll
                for (int nt = 0; nt < 8; nt++) {
                    mma_bf16(acc[mt][nt], ah[mt][0], ah[mt][1], ah[mt][2], ah[mt][3],
                             bh[nt][0], bh[nt][1]);
                    mma_bf16(acc[mt][nt], ah[mt][0], ah[mt][1], ah[mt][2], ah[mt][3],
                             bl[nt][0], bl[nt][1]);
                    mma_bf16(acc[mt][nt], al[mt][0], al[mt][1], al[mt][2], al[mt][3],
                             bh[nt][0], bh[nt][1]);
                }
        }
        __syncthreads();
        if (++bufi == 3) bufi = 0;
    }

#pragma unroll
    for (int mt = 0; mt < 2; mt++) {
        const int r = m0 + wm * 32 + mt * 16 + lr;
#pragma unroll
        for (int nt = 0; nt < 8; nt++) {
            const int cN = n0 + wn * 64 + nt * 8 + 2 * lc;
            *(float2*)(Cp + (size_t)r * N + cN) =
                make_float2(acc[mt][nt][0], acc[mt][nt][1]);
            *(float2*)(Cp + (size_t)(r + 8) * N + cN) =
                make_float2(acc[mt][nt][2], acc[mt][nt][3]);
        }
    }
}

// ============================================================
// RMS kernels
// ============================================================
__device__ __forceinline__ void rms_row(float* row, const float* g, int C,
                                        const float* mean32, int tid)
{
    float vr[4];
    int cnt = C >> 7;
    float ss = 0.f;
#pragma unroll 4
    for (int j = 0; j < cnt; j++) {
        int i = tid + j * 128;
        float v = row[i];
        if (mean32) v += mean32[i & 31];
        vr[j] = v;
        ss += v * v;
    }
#pragma unroll
    for (int o = 16; o; o >>= 1) ss += __shfl_xor_sync(~0u, ss, o);
    __shared__ float ws[4];
    if ((tid & 31) == 0) ws[tid >> 5] = ss;
    __syncthreads();
    float tot = ws[0] + ws[1] + ws[2] + ws[3];
    float r = rsqrtf(tot / (float)C + EPSc);
#pragma unroll 4
    for (int j = 0; j < cnt; j++) {
        int i = tid + j * 128;
        row[i] = vr[j] * r * g[i];
    }
}

__global__ void __launch_bounds__(128) rms3(
    float* pa, const float* ga, int Ca,
    float* pb, const float* gb, int Cb,
    float* pc, const float* gc, int Cc)
{
    int t = blockIdx.x;
    if (t < Tc)          rms_row(pa + (size_t)t * Ca, ga, Ca, nullptr, threadIdx.x);
    else if (t < 2 * Tc) rms_row(pb + (size_t)(t - Tc) * Cb, gb, Cb, nullptr, threadIdx.x);
    else                 rms_row(pc + (size_t)(t - 2 * Tc) * Cc, gc, Cc, nullptr, threadIdx.x);
}

__global__ void __launch_bounds__(128) rms2(
    float* pa, const float* ga, int Ca,
    float* pb, const float* gb, int Cb)
{
    int t = blockIdx.x;
    if (t < Tc) rms_row(pa + (size_t)t * Ca, ga, Ca, nullptr, threadIdx.x);
    else {
        t -= Tc;
        rms_row(pb + (size_t)t * Cb, gb, Cb, nullptr, threadIdx.x);
    }
}

// post-RMS with fused cross-coupling mean (head_mean folded in)
__global__ void __launch_bounds__(128) rms2m(
    float* __restrict__ pqc, const float* __restrict__ gq,
    float* __restrict__ pkc, const float* __restrict__ gk,
    const float* __restrict__ pq_pre, const float* __restrict__ pk_pre)
{
    __shared__ float mean[32];
    int t = blockIdx.x;
    const int tid = threadIdx.x;
    if (t < Tc) {
        // q row: mean over 4 kv heads of k_pre
        if (tid < 32) {
            const float* kr = pk_pre + (size_t)t * KVDc + tid;
            mean[tid] = GAINc * 0.25f * (kr[0] + kr[32] + kr[64] + kr[96]);
        }
        __syncthreads();
        rms_row(pqc + (size_t)t * LATc, gq, LATc, mean, tid);
    } else {
        t -= Tc;
        if (tid < 32) {
            const float* qr = pq_pre + (size_t)t * LATc + tid;
            float s = 0.f;
#pragma unroll
            for (int h = 0; h < 16; h++) s += qr[h * 32];
            mean[tid] = GAINc * 0.0625f * s;
        }
        __syncthreads();
        rms_row(pkc + (size_t)t * KVDc, gk, KVDc, mean, tid);
    }
}

__global__ void __launch_bounds__(128) rms_split(
    const float* __restrict__ x, const float* __restrict__ g,
    __nv_bfloat16* __restrict__ hi, __nv_bfloat16* __restrict__ lo)
{
    const int t = blockIdx.x;
    const float* row = x + (size_t)t * LATc;
    const int tid = threadIdx.x;
    float vr[4];
    float ss = 0.f;
#pragma unroll
    for (int j = 0; j < 4; j++) {
        float v = row[tid + j * 128];
        vr[j] = v;
        ss += v * v;
    }
#pragma unroll
    for (int o = 16; o; o >>= 1) ss += __shfl_xor_sync(~0u, ss, o);
    __shared__ float ws[4];
    if ((tid & 31) == 0) ws[tid >> 5] = ss;
    __syncthreads();
    float tot = ws[0] + ws[1] + ws[2] + ws[3];
    float r = rsqrtf(tot / (float)LATc + EPSc);
#pragma unroll
    for (int j = 0; j < 4; j++) {
        int i = tid + j * 128;
        float y = vr[j] * r * g[i];
        __nv_bfloat16 h, l;
        fsplit_bf16(y, h, l);
        hi[(size_t)t * LATc + i] = h;
        lo[(size_t)t * LATc + i] = l;
    }
}

// ============================================================
// Grouped causal conv (tiled)
// ============================================================
__global__ void __launch_bounds__(256) conv_causal_t(
    float* __restrict__ y, const float* __restrict__ x,
    const float* __restrict__ w, int C)
{
    __shared__ float ws[96][33];
    __shared__ float xs[66][32];
    const int tid = threadIdx.x;
    const int t0 = blockIdx.x * 64;
    const int base = blockIdx.y * 32;
    const int s0 = t0 & (Sc - 1);

    for (int idx = tid; idx < 3072; idx += 256) {
        int co = idx / 96;
        int r = idx - co * 96;
        ws[r][co] = w[(size_t)(base + co) * 96 + r];
    }
    for (int idx = tid; idx < 66 * 32; idx += 256) {
        int row = idx >> 5;
        int ci = idx & 31;
        int srow = s0 - 2 + row;
        xs[row][ci] = (srow >= 0 && row < 66)
            ? x[(size_t)(t0 - 2 + row) * C + base + ci] : 0.f;
    }
    __syncthreads();

    const int co = tid & 31;
    const int tg = tid >> 5;
#pragma unroll
    for (int tk = 0; tk < 8; tk++) {
        const int tt = tg * 8 + tk;
        float acc = 0.f;
#pragma unroll 8
        for (int ci = 0; ci < 32; ci++) {
#pragma unroll
            for (int j = 0; j < 3; j++)
                acc += ws[ci * 3 + j][co] * xs[tt + j][ci];
        }
        y[(size_t)(t0 + tt) * C + base + co] = acc;
    }
}

// ============================================================
// merged q+k per-head L2 norm + RoPE (table-driven) -> bf16 splits
// ============================================================
__global__ void __launch_bounds__(128) headnorm_rope2(
    const float* __restrict__ xq, const float* __restrict__ xk,
    __nv_bfloat16* __restrict__ qsh, __nv_bfloat16* __restrict__ qsl,
    __nv_bfloat16* __restrict__ ksh, __nv_bfloat16* __restrict__ ksl,
    const float* __restrict__ key_temp, const float2* __restrict__ rope)
{
    const int idx = blockIdx.x * 128 + threadIdx.x;
    const float* p;
    __nv_bfloat16 *oh, *ol;
    size_t off;
    int s, is_k;
    if (idx < Tc * NHc) {
        int t = idx >> 4;
        int h = idx & 15;
        off = (size_t)t * LATc + h * 32;
        p = xq + off; oh = qsh; ol = qsl;
        s = t & (Sc - 1);
        is_k = 0;
    } else {
        int j = idx - Tc * NHc;
        int t = j >> 2;
        int h = j & 3;
        off = (size_t)t * KVDc + h * 32;
        p = xk + off; oh = ksh; ol = ksl;
        s = t & (Sc - 1);
        is_k = 1;
    }
    float v[32];
    float ss = 0.f;
#pragma unroll
    for (int d = 0; d < 32; d++) { v[d] = p[d]; ss += v[d] * v[d]; }
    float n = fmaxf(sqrtf(ss), 1e-12f);
    float f = is_k ? (5.656854249492380f * key_temp[0] / n) : (1.0f / n);
    const float2* rt = rope + s * 16;
    uint32_t* oh32 = (uint32_t*)(oh + off);
    uint32_t* ol32 = (uint32_t*)(ol + off);
#pragma unroll
    for (int i = 0; i < 16; i++) {
        float2 cssn = rt[i];
        float x1 = v[2 * i] * f, x2 = v[2 * i + 1] * f;
        float r1 = x1 * cssn.x - x2 * cssn.y;
        float r2 = x1 * cssn.y + x2 * cssn.x;
        uint32_t hi, lo;
        pack_split2(r1, r2, hi, lo);
        oh32[i] = hi;
        ol32[i] = lo;
    }
}

// ============================================================
// V transpose + bf16 split
// ============================================================
__global__ void __launch_bounds__(256) vtrans(
    const float* __restrict__ v,
    __nv_bfloat16* __restrict__ vh, __nv_bfloat16* __restrict__ vl)
{
    __shared__ float ts[32][33];
    const int j0 = blockIdx.x * 32;
    const int bk = blockIdx.y;
    const int b = bk >> 2, kv = bk & 3;
    const int tid = threadIdx.x;
    {
        int ky = tid >> 3, d4 = (tid & 7) * 4;
        float4 val = *(const float4*)(v + (size_t)(b * Sc + j0 + ky) * KVDc + kv * 32 + d4);
        ts[ky][d4 + 0] = val.x; ts[ky][d4 + 1] = val.y;
        ts[ky][d4 + 2] = val.z; ts[ky][d4 + 3] = val.w;
    }
    __syncthreads();
    int d = tid >> 3, kp = (tid & 7) * 4;
    __nv_bfloat16 hb[4], lb[4];
#pragma unroll
    for (int i = 0; i < 4; i++)
        fsplit_bf16(ts[kp + i][d], hb[i], lb[i]);
    size_t dst = ((size_t)bk * 32 + d) * Sc + j0 + kp;
    *(uint2*)(vh + dst) = *(uint2*)hb;
    *(uint2*)(vl + dst) = *(uint2*)lb;
}

// ============================================================
// mma flash attention, fixed-bound softmax (no running max)
// ============================================================
__global__ void __launch_bounds__(256) flash_mma(
    float* __restrict__ o,
    const __nv_bfloat16* __restrict__ qh, const __nv_bfloat16* __restrict__ ql,
    const __nv_bfloat16* __restrict__ kh, const __nv_bfloat16* __restrict__ kl,
    const __nv_bfloat16* __restrict__ vth, const __nv_bfloat16* __restrict__ vtl,
    const float* __restrict__ key_temp)
{
    __shared__ uint32_t sK[2][2][64 * 20];
    __shared__ uint32_t sV[2][2][32 * 36];
    const int bh = blockIdx.y;
    const int b  = bh >> 4;
    const int h  = bh & 15;
    const int kv = h >> 2;
    const int sq0 = blockIdx.x * 128;
    const int tid = threadIdx.x;
    const int wq  = tid >> 5;
    const int lane = tid & 31;
    const int lr = lane >> 2;
    const int lc = lane & 3;
    // exact score bound: |q.k| <= 1 * sqrt(32)*|kt|
    const float M = 5.656854249492380f * fabsf(key_temp[0]) + 1e-3f;

    uint32_t qfh[2][4], qfl[2][4];
    {
        const int r0 = b * Sc + sq0 + wq * 16 + lr;
        const uint32_t* q0h = (const uint32_t*)(qh + (size_t)r0 * LATc + h * 32);
        const uint32_t* q8h = (const uint32_t*)(qh + (size_t)(r0 + 8) * LATc + h * 32);
        const uint32_t* q0l = (const uint32_t*)(ql + (size_t)r0 * LATc + h * 32);
        const uint32_t* q8l = (const uint32_t*)(ql + (size_t)(r0 + 8) * LATc + h * 32);
#pragma unroll
        for (int s = 0; s < 2; s++) {
            qfh[s][0] = q0h[8 * s + lc];
            qfh[s][1] = q8h[8 * s + lc];
            qfh[s][2] = q0h[8 * s + lc + 4];
            qfh[s][3] = q8h[8 * s + lc + 4];
            qfl[s][0] = q0l[8 * s + lc];
            qfl[s][1] = q8l[8 * s + lc];
            qfl[s][2] = q0l[8 * s + lc + 4];
            qfl[s][3] = q8l[8 * s + lc + 4];
        }
    }
    float oacc[4][4];
#pragma unroll
    for (int vn = 0; vn < 4; vn++)
#pragma unroll
        for (int c = 0; c < 4; c++) oacc[vn][c] = 0.f;
    float l0 = 0.f, l1 = 0.f;
    const int ntile = (sq0 >> 6) + 2;

#define LOAD_TILE(st, j0v) do { \
    const size_t gk = (size_t)(b * Sc + (j0v)); \
    for (int u = tid; u < 512; u += 256) { \
        int row = u >> 3, pp = u & 7; \
        CP_ASYNC8(smem_u32(&sK[st][0][row * 20 + pp * 2]), \
                  kh + (gk + row) * KVDc + kv * 32 + pp * 4); \
        CP_ASYNC8(smem_u32(&sK[st][1][row * 20 + pp * 2]), \
                  kl + (gk + row) * KVDc + kv * 32 + pp * 4); \
    } \
    { \
        int d = tid >> 3, q8 = tid & 7; \
        const size_t vs = ((size_t)(b * 4 + kv) * 32 + d) * Sc + (j0v) + q8 * 8; \
        CP_ASYNC16(smem_u32(&sV[st][0][d * 36 + q8 * 4]), vth + vs); \
        CP_ASYNC16(smem_u32(&sV[st][1][d * 36 + q8 * 4]), vtl + vs); \
    } \
} while (0)

    LOAD_TILE(0, 0);
    CP_COMMIT();

    for (int jt = 0; jt < ntile; jt++) {
        const int st = jt & 1;
        const int j0 = jt << 6;
        if (jt + 1 < ntile) {
            LOAD_TILE(st ^ 1, j0 + 64);
            CP_COMMIT();
            CP_WAIT(1);
        } else {
            CP_WAIT(0);
        }
        __syncthreads();

        float sacc[8][4];
#pragma unroll
        for (int nt = 0; nt < 8; nt++)
#pragma unroll
            for (int c = 0; c < 4; c++) sacc[nt][c] = 0.f;
#pragma unroll
        for (int s = 0; s < 2; s++) {
#pragma unroll
            for (int nt = 0; nt < 8; nt++) {
                const uint32_t* Kr0 = &sK[st][0][(nt * 8 + lr) * 20 + 8 * s + lc];
                const uint32_t* Kr1 = &sK[st][1][(nt * 8 + lr) * 20 + 8 * s + lc];
                uint32_t b0 = Kr0[0], b1 = Kr0[4];
                uint32_t c0 = Kr1[0], c1 = Kr1[4];
                mma_bf16(sacc[nt], qfh[s][0], qfh[s][1], qfh[s][2], qfh[s][3], b0, b1);
                mma_bf16(sacc[nt], qfh[s][0], qfh[s][1], qfh[s][2], qfh[s][3], c0, c1);
                mma_bf16(sacc[nt], qfl[s][0], qfl[s][1], qfl[s][2], qfl[s][3], b0, b1);
            }
        }
        const int r0 = sq0 + wq * 16 + lr;
        const int r1 = r0 + 8;
        const bool full = (j0 + 63) <= (sq0 + wq * 16);
        if (!full) {
#pragma unroll
            for (int nt = 0; nt < 8; nt++) {
                int kb = j0 + nt * 8 + 2 * lc;
                if (kb     > r0) sacc[nt][0] = -1e30f;
                if (kb + 1 > r0) sacc[nt][1] = -1e30f;
                if (kb     > r1) sacc[nt][2] = -1e30f;
                if (kb + 1 > r1) sacc[nt][3] = -1e30f;
            }
        }
#pragma unroll
        for (int s2 = 0; s2 < 4; s2++) {
            float p0a = fexp2((sacc[2 * s2][0] - M) * L2E);
            float p0b = fexp2((sacc[2 * s2][1] - M) * L2E);
            float p8a = fexp2((sacc[2 * s2][2] - M) * L2E);
            float p8b = fexp2((sacc[2 * s2][3] - M) * L2E);
            float q0a = fexp2((sacc[2 * s2 + 1][0] - M) * L2E);
            float q0b = fexp2((sacc[2 * s2 + 1][1] - M) * L2E);
            float q8a = fexp2((sacc[2 * s2 + 1][2] - M) * L2E);
            float q8b = fexp2((sacc[2 * s2 + 1][3] - M) * L2E);
            l0 += p0a + p0b + q0a + q0b;
            l1 += p8a + p8b + q8a + q8b;
            uint32_t pha[4], pla[4];
            pack_split2(p0a, p0b, pha[0], pla[0]);
            pack_split2(p8a, p8b, pha[1], pla[1]);
            pack_split2(q0a, q0b, pha[2], pla[2]);
            pack_split2(q8a, q8b, pha[3], pla[3]);
#pragma unroll
            for (int vn = 0; vn < 4; vn++) {
                const uint32_t* Vr0 = &sV[st][0][(vn * 8 + lr) * 36 + 8 * s2 + lc];
                const uint32_t* Vr1 = &sV[st][1][(vn * 8 + lr) * 36 + 8 * s2 + lc];
                uint32_t b0 = Vr0[0], b1 = Vr0[4];
                uint32_t c0 = Vr1[0], c1 = Vr1[4];
                mma_bf16(oacc[vn], pha[0], pha[1], pha[2], pha[3], b0, b1);
                mma_bf16(oacc[vn], pha[0], pha[1], pha[2], pha[3], c0, c1);
                mma_bf16(oacc[vn], pla[0], pla[1], pla[2], pla[3], b0, b1);
            }
        }
        __syncthreads();
    }

    l0 += __shfl_xor_sync(~0u, l0, 1);
    l0 += __shfl_xor_sync(~0u, l0, 2);
    l1 += __shfl_xor_sync(~0u, l1, 1);
    l1 += __shfl_xor_sync(~0u, l1, 2);
    float i0 = 1.f / l0, i1 = 1.f / l1;
    const int gr0 = b * Sc + sq0 + wq * 16 + lr;
    float* o0 = o + (size_t)gr0 * LATc + h * 32;
    float* o8 = o + (size_t)(gr0 + 8) * LATc + h * 32;
#pragma unroll
    for (int vn = 0; vn < 4; vn++) {
        *(float2*)(o0 + vn * 8 + 2 * lc) = make_float2(oacc[vn][0] * i0, oacc[vn][1] * i0);
        *(float2*)(o8 + vn * 8 + 2 * lc) = make_float2(oacc[vn][2] * i1, oacc[vn][3] * i1);
    }
}

// ============================================================
// host launcher
// ============================================================
extern "C" void kernel_launch(void* const* d_in, const int* in_sizes, int n_in,
                              void* d_out, int out_size)
{
    const float* x        = (const float*)d_in[0];
    const float* w_q      = (const float*)d_in[1];
    const float* w_k      = (const float*)d_in[2];
    const float* w_v      = (const float*)d_in[3];
    const float* g_latent = (const float*)d_in[4];
    const float* g_kv     = (const float*)d_in[5];
    const float* conv_q_w = (const float*)d_in[6];
    const float* conv_k_w = (const float*)d_in[7];
    const float* g_conv   = (const float*)d_in[8];
    const float* g_kconv  = (const float*)d_in[9];
    const float* g_postq  = (const float*)d_in[10];
    const float* g_postk  = (const float*)d_in[11];
    const float* key_temp = (const float*)d_in[12];
    const float* g_preout = (const float*)d_in[13];
    const float* w_o      = (const float*)d_in[14];
    float* out = (float*)d_out;

    float *pq, *pk, *pv, *pqc, *pkc, *po;
    float2* prt;
    __nv_bfloat16 *pxh, *pxl, *pwh, *pwl, *pph, *ppl;
    __nv_bfloat16 *pqh, *pql2, *pkh, *pkl, *pvth, *pvtl;
    cudaGetSymbolAddress((void**)&pq,  g_q);
    cudaGetSymbolAddress((void**)&pk,  g_k);
    cudaGetSymbolAddress((void**)&pv,  g_v);
    cudaGetSymbolAddress((void**)&pqc, g_qc);
    cudaGetSymbolAddress((void**)&pkc, g_kc);
    cudaGetSymbolAddress((void**)&po,  g_o);
    cudaGetSymbolAddress((void**)&prt, g_rope);
    cudaGetSymbolAddress((void**)&pxh, gb_xh);
    cudaGetSymbolAddress((void**)&pxl, gb_xl);
    cudaGetSymbolAddress((void**)&pwh, gb_wh);
    cudaGetSymbolAddress((void**)&pwl, gb_wl);
    cudaGetSymbolAddress((void**)&pph, gb_ph);
    cudaGetSymbolAddress((void**)&ppl, gb_pl);
    cudaGetSymbolAddress((void**)&pqh, gb_qh);
    cudaGetSymbolAddress((void**)&pql2, gb_ql);
    cudaGetSymbolAddress((void**)&pkh, gb_kh);
    cudaGetSymbolAddress((void**)&pkl, gb_kl);
    cudaGetSymbolAddress((void**)&pvth, gb_vth);
    cudaGetSymbolAddress((void**)&pvtl, gb_vtl);

    cudaFuncSetAttribute(gemm_bf16, cudaFuncAttributeMaxDynamicSharedMemorySize, GEMM_SMEM);

    // 0) rope tables + pre-splits
    rope_tab<<<(Sc * 16 + 255) / 256, 256>>>(prt);
    split_arr<<<(Tc * Dc / 4 + 255) / 256, 256>>>(pxh, pxl, x, Tc * Dc / 4);
    split_w4<<<(WTOT / 4 + 255) / 256, 256>>>(pwh, pwl, w_q, w_k, w_v, w_o);

    // 1) fused q/k/v projections
    gemm_bf16<<<dim3(6, Tc / 128), 256, GEMM_SMEM>>>(
        pxh, pxl, Dc, pwh, pwl,
        OFF_WQ, pq, 4, LATc, OFF_WK, pk, OFF_WV, pv);

    // 2) first RMS norms
    rms3<<<3 * Tc, 128>>>(pq, g_latent, LATc, pk, g_kv, KVDc, pv, g_kv, KVDc);

    // 3) causal grouped conv + RMS
    conv_causal_t<<<dim3(Tc / 64, LATc / 32), 256>>>(pqc, pq, conv_q_w, LATc);
    conv_causal_t<<<dim3(Tc / 64, KVDc / 32), 256>>>(pkc, pk, conv_k_w, KVDc);
    rms2<<<2 * Tc, 128>>>(pqc, g_conv, LATc, pkc, g_kconv, KVDc);

    // 4) post RMS with fused cross-coupling mean
    rms2m<<<2 * Tc, 128>>>(pqc, g_postq, pkc, g_postk, pq, pk);

    // 5) head norm + RoPE (table) -> bf16 splits; V transpose+split
    headnorm_rope2<<<(Tc * (NHc + NKVc)) / 128, 128>>>(
        pqc, pkc, pqh, pql2, pkh, pkl, key_temp, prt);
    vtrans<<<dim3(Sc / 32, Bc * NKVc), 256>>>(pv, pvth, pvtl);

    // 6) mma causal attention
    flash_mma<<<dim3(Sc / 128, Bc * NHc), 256>>>(
        po, pqh, pql2, pkh, pkl, pvth, pvtl, key_temp);

    // 7) pre-out RMS + split, then output projection
    rms_split<<<Tc, 128>>>(po, g_preout, pph, ppl);
    gemm_bf16<<<dim3(16, Tc / 128), 256, GEMM_SMEM>>>(
        pph, ppl, LATc, pwh, pwl,
        OFF_WO, out, 16, Dc, 0, nullptr, 0, nullptr);
}